// round 7
// baseline (speedup 1.0000x reference)
#include <cuda_runtime.h>
#include <cuda_fp16.h>
#include <math.h>
#include <stdint.h>

#define BB 64
#define SS 4096
#define HH 256
#define NTILES 2048            // BB*SS/128

// ---------------- device-global scratch (no allocation allowed) -------------
__device__ float g_u[BB * HH];            // W_t @ o_last per batch (fp32)
__device__ uint4 g_Bh[16 * 16 * 32];      // W_F fp16 m16n8k16 B-fragment image (128 KB)
__device__ float g_pT[NTILES * HH];
__device__ float g_pF[NTILES * HH];
__device__ float g_mT[NTILES], g_sT[NTILES], g_mF[NTILES], g_sF[NTILES];

// ---------------- SMEM map (bytes) ------------------------------------------
#define AH_OFF    0            // 2 slots x (128 rows x 128B fp16) = 32768
#define B_OFF     32768        // 3 slots x 32768 = 98304
#define USH_OFF   131072       // 256 floats
#define VSH_OFF   132096       // 256 floats
#define SCT_OFF   133120       // 128 floats
#define SCF_OFF   133632       // 128 floats
#define SCFR_OFF  134144       // 8 x 128 floats = 4096
#define RED_OFF   138240       // 32 floats
#define SMEM_TOTAL 138368
// weighted-sum partials reuse the B region after the mainloop:
#define PTS_OFF   B_OFF                 // 8 x 256 floats = 8192
#define PFS_OFF   (B_OFF + 8192)        // 8 x 256 floats

// ---------------- helpers ----------------------------------------------------
__device__ __forceinline__ uint32_t packh2(float lo, float hi) {
    __half2 h = __floats2half2_rn(lo, hi);
    return *(uint32_t*)&h;
}
__device__ __forceinline__ float tanha(float x) {
    float y;
    asm("tanh.approx.f32 %0, %1;" : "=f"(y) : "f"(x));
    return y;
}
__device__ __forceinline__ void mma16(float* c, uint32_t a0, uint32_t a1,
                                      uint32_t a2, uint32_t a3,
                                      uint32_t b0, uint32_t b1) {
    asm volatile(
        "mma.sync.aligned.m16n8k16.row.col.f32.f16.f16.f32 "
        "{%0,%1,%2,%3}, {%4,%5,%6,%7}, {%8,%9}, {%0,%1,%2,%3};"
        : "+f"(c[0]), "+f"(c[1]), "+f"(c[2]), "+f"(c[3])
        : "r"(a0), "r"(a1), "r"(a2), "r"(a3), "r"(b0), "r"(b1));
}
__device__ __forceinline__ void ldsm4(uint32_t* a, uint32_t addr) {
    asm volatile("ldmatrix.sync.aligned.m8n8.x4.shared.b16 {%0,%1,%2,%3}, [%4];"
                 : "=r"(a[0]), "=r"(a[1]), "=r"(a[2]), "=r"(a[3]) : "r"(addr));
}
#define CP16(dst, src) \
    asm volatile("cp.async.cg.shared.global [%0], [%1], 16;" :: "r"(dst), "l"(src) : "memory")
#define CPCOMMIT() asm volatile("cp.async.commit_group;" ::: "memory")
template<int N> __device__ __forceinline__ void cpwait() {
    asm volatile("cp.async.wait_group %0;" :: "n"(N) : "memory");
}
__device__ __forceinline__ uint32_t s2u(const void* p) {
    uint32_t a;
    asm("{ .reg .u64 t; cvta.to.shared.u64 t, %1; cvt.u32.u64 %0, t; }" : "=r"(a) : "l"(p));
    return a;
}

// ---------------------------------------------------------------------------
// k_init: blocks 0..15 build the W_F fp16 B-fragment image;
//         blocks 16..79 compute u[b] = W_t @ o_last[b] (exact fp32).
// grid = 80, block = 512.
// ---------------------------------------------------------------------------
__global__ void __launch_bounds__(512)
k_init(const float* __restrict__ o, const float* __restrict__ Wt,
       const float* __restrict__ WF) {
    int tid = threadIdx.x;
    if (blockIdx.x < 16) {
        int t = blockIdx.x;              // kstep 0..15
        int p = tid >> 5, l = tid & 31;
        int rq = l >> 2, cq = l & 3;
        int k0 = t * 16 + 2 * cq;
        int na = p * 16 + rq, nb = na + 8;
        uint4 q;
        q.x = packh2(WF[k0 * HH + na],       WF[(k0 + 1) * HH + na]);
        q.y = packh2(WF[(k0 + 8) * HH + na], WF[(k0 + 9) * HH + na]);
        q.z = packh2(WF[k0 * HH + nb],       WF[(k0 + 1) * HH + nb]);
        q.w = packh2(WF[(k0 + 8) * HH + nb], WF[(k0 + 9) * HH + nb]);
        g_Bh[(t * 16 + p) * 32 + l] = q;
    } else {
        int b = blockIdx.x - 16;
        __shared__ float olast[HH];
        if (tid < HH) olast[tid] = o[((size_t)b * SS + (SS - 1)) * HH + tid];
        __syncthreads();
        if (tid < HH) {
            float acc = 0.f;
            const float* wrow = Wt + tid * HH;
#pragma unroll 8
            for (int k = 0; k < HH; k++) acc = fmaf(wrow[k], olast[k], acc);
            g_u[b * HH + tid] = acc;
        }
    }
}

// ---------------------------------------------------------------------------
// k_main: fused feature GEMM (fp16 mma, warp tile 64x32) + exact fp32 time
//         scores (folded into A prefetch) + tanh·v_F + split-softmax partials
//         + exact fp32 weighted sums. grid=2048, block=512.
// ---------------------------------------------------------------------------
__global__ void __launch_bounds__(512, 1)
k_main(const float* __restrict__ o, const float* __restrict__ vF) {
    extern __shared__ __align__(16) char smem[];
    const uint32_t sb = s2u(smem);
    const int tid = threadIdx.x, lane = tid & 31, wid = tid >> 5;
    const int tile = blockIdx.x;
    const int b = tile >> 5, s0 = (tile & 31) << 7;
    const int mw = wid & 1;   // M half (64 rows)
    const int nw = wid >> 1;  // N eighth (32 cols)
    const int rq = lane >> 2, cq = lane & 3;

    float* ush  = (float*)(smem + USH_OFF);
    float* vsh  = (float*)(smem + VSH_OFF);
    float* scT  = (float*)(smem + SCT_OFF);
    float* scF  = (float*)(smem + SCF_OFF);
    float* scFr = (float*)(smem + SCFR_OFF);
    float* red  = (float*)(smem + RED_OFF);

    const float* obase = o + ((size_t)(b * SS + s0)) * HH;

    // ---- B chunk issue via cp.async: 32 KB (4 ksteps of the fragment image) --
    auto issueB = [&](int c) {
        uint32_t bdst = sb + B_OFF + (c % 3) * 32768;
        const uint4* bsrc = g_Bh + c * 2048;
#pragma unroll
        for (int j = 0; j < 4; j++) {
            int idx = tid + j * 512;
            CP16(bdst + idx * 16, (const void*)(bsrc + idx));
        }
        CPCOMMIT();
    };

    // ---- A prefetch (LDG->fp32 regs), fold time-score FMAs, fp16 STS ----
    // thread: row = tid>>2 (0..127), q = tid&3 (16 cols of the 64-col chunk)
    const int arow = tid >> 2, q = tid & 3;
    const float4* aldg = (const float4*)obase + (size_t)arow * 64 + q * 4;
    const uint32_t xr = (uint32_t)((arow & 7) << 4);
    const uint32_t abase_sts = (uint32_t)arow * 128;

    float4 pf[4];
    float sT = 0.f;
    auto ldgA = [&](int c) {
#pragma unroll
        for (int k = 0; k < 4; k++) pf[k] = __ldg(aldg + c * 16 + k);
    };
    auto stsA = [&](int c) {
        const float* ub = ush + c * 64 + q * 16;
#pragma unroll
        for (int k = 0; k < 4; k++) {
            sT = fmaf(pf[k].x, ub[4 * k],     sT);
            sT = fmaf(pf[k].y, ub[4 * k + 1], sT);
            sT = fmaf(pf[k].z, ub[4 * k + 2], sT);
            sT = fmaf(pf[k].w, ub[4 * k + 3], sT);
        }
        uint4 qa, qb;
        qa.x = packh2(pf[0].x, pf[0].y); qa.y = packh2(pf[0].z, pf[0].w);
        qa.z = packh2(pf[1].x, pf[1].y); qa.w = packh2(pf[1].z, pf[1].w);
        qb.x = packh2(pf[2].x, pf[2].y); qb.y = packh2(pf[2].z, pf[2].w);
        qb.z = packh2(pf[3].x, pf[3].y); qb.w = packh2(pf[3].z, pf[3].w);
        uint32_t base = (uint32_t)((c & 1) * 16384) + abase_sts;
        *(uint4*)(smem + base + (((uint32_t)(q * 32))      ^ xr)) = qa;
        *(uint4*)(smem + base + (((uint32_t)(q * 32 + 16)) ^ xr)) = qb;
    };

    // ---- prologue ----
    issueB(0); issueB(1);
    if (tid < 256) {
        ush[tid] = __ldg(&g_u[b * HH + tid]);
        vsh[tid] = __ldg(&vF[tid]);
    }
    ldgA(0);
    __syncthreads();          // ush visible before stsA(0)
    stsA(0);
    ldgA(1);

    // ---- ldmatrix lane addressing (per mi, 4 m16 tiles) ----
    const uint32_t half16 = (uint32_t)((lane >> 4) << 4);
    uint32_t lbase[4], lxor[4];
#pragma unroll
    for (int mi = 0; mi < 4; mi++) {
        uint32_t r = (uint32_t)(mw * 64 + mi * 16 + (lane & 15));
        lbase[mi] = sb + AH_OFF + r * 128;
        lxor[mi] = (r & 7) << 4;
    }

    float acc[4][4][4];
#pragma unroll
    for (int mi = 0; mi < 4; mi++)
#pragma unroll
        for (int ni = 0; ni < 4; ni++)
#pragma unroll
            for (int j = 0; j < 4; j++) acc[mi][ni][j] = 0.f;

    // ---- mainloop over 4 K-chunks of 64 ----
#pragma unroll
    for (int c = 0; c < 4; c++) {
        if (c < 3) cpwait<1>(); else cpwait<0>();
        __syncthreads();
        if (c + 2 < 4) issueB(c + 2);
        if (c + 1 < 4) {
            stsA(c + 1);
            if (c + 2 < 4) ldgA(c + 2);
        }

        const uint4* Bsl = (const uint4*)(smem + B_OFF + (c % 3) * 32768);
        const uint32_t aoff = (uint32_t)((c & 1) * 16384);
#pragma unroll
        for (int tt = 0; tt < 4; tt++) {
            uint32_t a[4][4];
#pragma unroll
            for (int mi = 0; mi < 4; mi++)
                ldsm4(a[mi], lbase[mi] + aoff + (((uint32_t)(tt * 32) + half16) ^ lxor[mi]));
            uint4 bq0 = Bsl[(tt * 16 + nw * 2) * 32 + lane];
            uint4 bq1 = Bsl[(tt * 16 + nw * 2 + 1) * 32 + lane];
#pragma unroll
            for (int mi = 0; mi < 4; mi++) {
                mma16(acc[mi][0], a[mi][0], a[mi][1], a[mi][2], a[mi][3], bq0.x, bq0.y);
                mma16(acc[mi][1], a[mi][0], a[mi][1], a[mi][2], a[mi][3], bq0.z, bq0.w);
                mma16(acc[mi][2], a[mi][0], a[mi][1], a[mi][2], a[mi][3], bq1.x, bq1.y);
                mma16(acc[mi][3], a[mi][0], a[mi][1], a[mi][2], a[mi][3], bq1.z, bq1.w);
            }
        }
    }

    // ---- feature scores: sf[r] = sum_n tanh(z[r,n]) * v[n] ----
#pragma unroll
    for (int mi = 0; mi < 4; mi++) {
        float s0a = 0.f, s1a = 0.f;
#pragma unroll
        for (int ni = 0; ni < 4; ni++) {
            int n = nw * 32 + ni * 8 + cq * 2;
            float v0 = vsh[n], v1 = vsh[n + 1];
            s0a = fmaf(tanha(acc[mi][ni][0]), v0, s0a);
            s0a = fmaf(tanha(acc[mi][ni][1]), v1, s0a);
            s1a = fmaf(tanha(acc[mi][ni][2]), v0, s1a);
            s1a = fmaf(tanha(acc[mi][ni][3]), v1, s1a);
        }
        s0a += __shfl_xor_sync(0xFFFFFFFFu, s0a, 1);
        s0a += __shfl_xor_sync(0xFFFFFFFFu, s0a, 2);
        s1a += __shfl_xor_sync(0xFFFFFFFFu, s1a, 1);
        s1a += __shfl_xor_sync(0xFFFFFFFFu, s1a, 2);
        if (cq == 0) {
            int r = mw * 64 + mi * 16 + rq;
            scFr[nw * 128 + r] = s0a;
            scFr[nw * 128 + r + 8] = s1a;
        }
    }

    // ---- exact fp32 time scores: reduce over the 4 threads sharing a row ----
    sT += __shfl_xor_sync(0xFFFFFFFFu, sT, 1);
    sT += __shfl_xor_sync(0xFFFFFFFFu, sT, 2);
    if ((lane & 3) == 0) scT[arow] = sT;
    __syncthreads();
    if (tid < 128) {
        float a = 0.f;
#pragma unroll
        for (int g = 0; g < 8; g++) a += scFr[g * 128 + tid];
        scF[tid] = a;
    }
    __syncthreads();

    // ---- split-softmax partials for both arrays (threads 0..255 active) ----
    float vv = 0.f, ee = 0.f;
    float* arr = (tid < 128) ? scT : scF;
    int i = tid & 127;
    if (tid < 256) {
        vv = arr[i];
        float m = vv;
#pragma unroll
        for (int off = 16; off; off >>= 1)
            m = fmaxf(m, __shfl_xor_sync(0xFFFFFFFFu, m, off));
        if (lane == 0) red[wid] = m;
    }
    __syncthreads();
    float M = 0.f;
    if (tid < 256) {
        M = (tid < 128)
            ? fmaxf(fmaxf(red[0], red[1]), fmaxf(red[2], red[3]))
            : fmaxf(fmaxf(red[4], red[5]), fmaxf(red[6], red[7]));
        ee = __expf(vv - M);
        float s = ee;
#pragma unroll
        for (int off = 16; off; off >>= 1)
            s += __shfl_xor_sync(0xFFFFFFFFu, s, off);
        if (lane == 0) red[16 + wid] = s;
    }
    __syncthreads();
    if (tid < 256) arr[i] = ee;
    __syncthreads();
    if (tid == 0)   { g_mT[tile] = M; g_sT[tile] = red[16] + red[17] + red[18] + red[19]; }
    if (tid == 128) { g_mF[tile] = M; g_sF[tile] = red[20] + red[21] + red[22] + red[23]; }

    // ---- exact fp32 weighted sums: re-read o from L2 via LDG.128 ----
    {
        int g = tid >> 6, hc = tid & 63;
        const float4* orow = (const float4*)obase + (size_t)(g * 16) * 64 + hc;
        float4 aT = {0.f, 0.f, 0.f, 0.f}, aF = {0.f, 0.f, 0.f, 0.f};
#pragma unroll 8
        for (int r = 0; r < 16; r++) {
            float4 ov = __ldg(orow + (size_t)r * 64);
            float wT = scT[g * 16 + r], wF = scF[g * 16 + r];
            aT.x = fmaf(wT, ov.x, aT.x); aT.y = fmaf(wT, ov.y, aT.y);
            aT.z = fmaf(wT, ov.z, aT.z); aT.w = fmaf(wT, ov.w, aT.w);
            aF.x = fmaf(wF, ov.x, aF.x); aF.y = fmaf(wF, ov.y, aF.y);
            aF.z = fmaf(wF, ov.z, aF.z); aF.w = fmaf(wF, ov.w, aF.w);
        }
        float* pTs = (float*)(smem + PTS_OFF);
        float* pFs = (float*)(smem + PFS_OFF);
        ((float4*)(pTs + g * 256))[hc] = aT;
        ((float4*)(pFs + g * 256))[hc] = aF;
    }
    __syncthreads();
    {
        float* pTs = (float*)(smem + PTS_OFF);
        float* pFs = (float*)(smem + PFS_OFF);
        if (tid < 256) {
            float a = 0.f;
#pragma unroll
            for (int g = 0; g < 8; g++) a += pTs[g * 256 + tid];
            g_pT[tile * HH + tid] = a;
        } else {
            int j = tid - 256;
            float a = 0.f;
#pragma unroll
            for (int g = 0; g < 8; g++) a += pFs[g * 256 + j];
            g_pF[tile * HH + j] = a;
        }
    }
}

// ---------------------------------------------------------------------------
// k_combine: exact split-softmax merge. grid = (BB, 2): y=0 time, y=1 feature.
// ---------------------------------------------------------------------------
__global__ void k_combine(float* __restrict__ out) {
    int b = blockIdx.x, h = threadIdx.x, which = blockIdx.y;
    const float* gm = which ? g_mF : g_mT;
    const float* gs = which ? g_sF : g_sT;
    const float* gp = which ? g_pF : g_pT;
    float M = -1e30f;
#pragma unroll
    for (int c = 0; c < 32; c++) M = fmaxf(M, gm[b * 32 + c]);
    float S = 0.f, oV = 0.f;
#pragma unroll
    for (int c = 0; c < 32; c++) {
        int t = b * 32 + c;
        float w = __expf(gm[t] - M);
        S = fmaf(w, gs[t], S);
        oV = fmaf(w, __ldg(&gp[t * HH + h]), oV);
    }
    out[b * 2 * HH + which * HH + h] = oV / S;
}

// ---------------------------------------------------------------------------
extern "C" void kernel_launch(void* const* d_in, const int* in_sizes, int n_in,
                              void* d_out, int out_size) {
    const float* o  = (const float*)d_in[0];
    const float* Wt = (const float*)d_in[1];
    const float* WF = (const float*)d_in[2];
    const float* vF = (const float*)d_in[3];
    float* out = (float*)d_out;

    cudaFuncSetAttribute(k_main, cudaFuncAttributeMaxDynamicSharedMemorySize, SMEM_TOTAL);

    k_init<<<80, 512>>>(o, Wt, WF);
    k_main<<<NTILES, 512, SMEM_TOTAL>>>(o, vF);
    k_combine<<<dim3(BB, 2), HH>>>(out);
}

// round 8
// speedup vs baseline: 1.2620x; 1.2620x over previous
#include <cuda_runtime.h>
#include <cuda_fp16.h>
#include <math.h>
#include <stdint.h>

#define BB 64
#define SS 4096
#define HH 256
#define NTILES 2048            // BB*SS/128

// ---------------- device-global scratch (no allocation allowed) -------------
__device__ float g_u[BB * HH];            // W_t @ o_last per batch (fp32)
__device__ uint4 g_Bh[16 * 16 * 32];      // W_F fp16 m16n8k16 B-fragment image (128 KB)
__device__ float g_pT[NTILES * HH];
__device__ float g_pF[NTILES * HH];
__device__ float g_mT[NTILES], g_sT[NTILES], g_mF[NTILES], g_sF[NTILES];

// ---------------- SMEM map (bytes) ------------------------------------------
#define AH_OFF    0            // 2 slots x (128 rows x 64B fp16) = 16384
#define B_OFF     16384        // 3 slots x 16384 = 49152 (fp16 fragments)
#define USH_OFF   65536        // 256 floats (u, fp32)
#define VSH_OFF   66560        // 256 floats
#define SCT_OFF   67584        // 128 floats
#define SCF_OFF   68096        // 128 floats
#define SCFR_OFF  68608        // 4 x 128 floats = 2048
#define RED_OFF   70656        // 32 floats
#define SMEM_TOTAL 70784
// weighted-sum partials reuse the B region after the mainloop:
#define PTS_OFF   B_OFF                 // 8 x 256 floats = 8192
#define PFS_OFF   (B_OFF + 8192)        // 8 x 256 floats

// ---------------- helpers ----------------------------------------------------
__device__ __forceinline__ uint32_t packh2(float lo, float hi) {
    __half2 h = __floats2half2_rn(lo, hi);
    return *(uint32_t*)&h;
}
__device__ __forceinline__ float tanha(float x) {
    float y;
    asm("tanh.approx.f32 %0, %1;" : "=f"(y) : "f"(x));
    return y;
}
__device__ __forceinline__ void mma16(float* c, uint32_t a0, uint32_t a1,
                                      uint32_t a2, uint32_t a3,
                                      uint32_t b0, uint32_t b1) {
    asm volatile(
        "mma.sync.aligned.m16n8k16.row.col.f32.f16.f16.f32 "
        "{%0,%1,%2,%3}, {%4,%5,%6,%7}, {%8,%9}, {%0,%1,%2,%3};"
        : "+f"(c[0]), "+f"(c[1]), "+f"(c[2]), "+f"(c[3])
        : "r"(a0), "r"(a1), "r"(a2), "r"(a3), "r"(b0), "r"(b1));
}
__device__ __forceinline__ void ldsm4(uint32_t* a, uint32_t addr) {
    asm volatile("ldmatrix.sync.aligned.m8n8.x4.shared.b16 {%0,%1,%2,%3}, [%4];"
                 : "=r"(a[0]), "=r"(a[1]), "=r"(a[2]), "=r"(a[3]) : "r"(addr));
}
#define CP16(dst, src) \
    asm volatile("cp.async.cg.shared.global [%0], [%1], 16;" :: "r"(dst), "l"(src) : "memory")
#define CPCOMMIT() asm volatile("cp.async.commit_group;" ::: "memory")
template<int N> __device__ __forceinline__ void cpwait() {
    asm volatile("cp.async.wait_group %0;" :: "n"(N) : "memory");
}
__device__ __forceinline__ uint32_t s2u(const void* p) {
    uint32_t a;
    asm("{ .reg .u64 t; cvta.to.shared.u64 t, %1; cvt.u32.u64 %0, t; }" : "=r"(a) : "l"(p));
    return a;
}

// ---------------------------------------------------------------------------
// k_init: blocks 0..15 build the W_F fp16 B-fragment image (512 thr);
//         blocks 16..1039 compute u[b][h] = dot(W_t[h], o_last[b]) — one warp
//         per (b,h) pair, lanes stride k (fully coalesced LDG), shfl reduce.
// grid = 1040, block = 512.
// ---------------------------------------------------------------------------
__global__ void __launch_bounds__(512)
k_init(const float* __restrict__ o, const float* __restrict__ Wt,
       const float* __restrict__ WF) {
    int tid = threadIdx.x;
    if (blockIdx.x < 16) {
        int t = blockIdx.x;              // kstep 0..15
        int p = tid >> 5, l = tid & 31;
        int rq = l >> 2, cq = l & 3;
        int k0 = t * 16 + 2 * cq;
        int na = p * 16 + rq, nb = na + 8;
        uint4 q;
        q.x = packh2(WF[k0 * HH + na],       WF[(k0 + 1) * HH + na]);
        q.y = packh2(WF[(k0 + 8) * HH + na], WF[(k0 + 9) * HH + na]);
        q.z = packh2(WF[k0 * HH + nb],       WF[(k0 + 1) * HH + nb]);
        q.w = packh2(WF[k0 * HH + nb + 8 * HH], WF[(k0 + 9) * HH + nb]);
        // NOTE: q.w first element must be WF[(k0+8)*HH+nb]; write explicitly:
        q.w = packh2(WF[(k0 + 8) * HH + nb], WF[(k0 + 9) * HH + nb]);
        g_Bh[(t * 16 + p) * 32 + l] = q;
    } else {
        int idx = (blockIdx.x - 16) * 16 + (tid >> 5);   // warp id 0..16383
        int lane = tid & 31;
        int b = idx >> 8, h = idx & 255;
        const float* wrow = Wt + h * HH;
        const float* olast = o + ((size_t)b * SS + (SS - 1)) * HH;
        float acc = 0.f;
#pragma unroll
        for (int j = 0; j < 8; j++) {
            int k = j * 32 + lane;
            acc = fmaf(__ldg(&wrow[k]), __ldg(&olast[k]), acc);
        }
#pragma unroll
        for (int off = 16; off; off >>= 1)
            acc += __shfl_xor_sync(0xFFFFFFFFu, acc, off);
        if (lane == 0) g_u[b * HH + h] = acc;
    }
}

// ---------------------------------------------------------------------------
// k_main: fused feature GEMM (fp16 mma, ldmatrix, warp tile 32x64) + exact
//         fp32 time scores (folded into A prefetch) + tanh·v_F +
//         split-softmax partials + exact fp32 weighted sums (LDG re-read).
// grid=2048, block=512.   [identical to the round-6 version]
// ---------------------------------------------------------------------------
__global__ void __launch_bounds__(512, 1)
k_main(const float* __restrict__ o, const float* __restrict__ vF) {
    extern __shared__ __align__(16) char smem[];
    const uint32_t sb = s2u(smem);
    const int tid = threadIdx.x, lane = tid & 31, wid = tid >> 5;
    const int tile = blockIdx.x;
    const int b = tile >> 5, s0 = (tile & 31) << 7;
    const int mw = wid & 3;   // M quarter (32 rows)
    const int nw = wid >> 2;  // N quarter (64 cols)
    const int rq = lane >> 2, cq = lane & 3;

    float* ush  = (float*)(smem + USH_OFF);
    float* vsh  = (float*)(smem + VSH_OFF);
    float* scT  = (float*)(smem + SCT_OFF);
    float* scF  = (float*)(smem + SCF_OFF);
    float* scFr = (float*)(smem + SCFR_OFF);
    float* red  = (float*)(smem + RED_OFF);

    const float* obase = o + ((size_t)(b * SS + s0)) * HH;

    // ---- B chunk issue via cp.async (fragment image, 16 KB/chunk) ----
    auto issueB = [&](int c) {
        uint32_t bdst = sb + B_OFF + (c % 3) * 16384;
        const uint4* bsrc = g_Bh + c * 1024;
#pragma unroll
        for (int j = 0; j < 2; j++) {
            int idx = tid + j * 512;
            CP16(bdst + idx * 16, (const void*)(bsrc + idx));
        }
        CPCOMMIT();
    };

    // ---- A prefetch (LDG->fp32 regs), fold time-score FMAs, fp16 STS ----
    const int arow = tid >> 2, q = tid & 3;
    const float4* aldg = (const float4*)obase + (size_t)arow * 64 + q * 2;
    const uint32_t axor = (uint32_t)(((arow >> 1) & 3) << 4);
    const uint32_t asts_off = AH_OFF + (uint32_t)arow * 64 + (((uint32_t)q * 16) ^ axor);

    float4 pf[2][2];
    float sT = 0.f;
    auto ldgA = [&](int c, int slot) {
        pf[slot][0] = __ldg(aldg + c * 8);
        pf[slot][1] = __ldg(aldg + c * 8 + 1);
    };
    auto stsA = [&](int c, int slot) {
        const float4 u0 = *(const float4*)(ush + c * 32 + q * 8);
        const float4 u1 = *(const float4*)(ush + c * 32 + q * 8 + 4);
        float4 a0 = pf[slot][0], a1 = pf[slot][1];
        sT = fmaf(a0.x, u0.x, sT); sT = fmaf(a0.y, u0.y, sT);
        sT = fmaf(a0.z, u0.z, sT); sT = fmaf(a0.w, u0.w, sT);
        sT = fmaf(a1.x, u1.x, sT); sT = fmaf(a1.y, u1.y, sT);
        sT = fmaf(a1.z, u1.z, sT); sT = fmaf(a1.w, u1.w, sT);
        uint4 qq;
        qq.x = packh2(a0.x, a0.y); qq.y = packh2(a0.z, a0.w);
        qq.z = packh2(a1.x, a1.y); qq.w = packh2(a1.z, a1.w);
        *(uint4*)(smem + (c & 1) * 8192 + asts_off) = qq;
    };

    // ---- prologue ----
    issueB(0); issueB(1);
    if (tid < 256) {
        ush[tid] = __ldg(&g_u[b * HH + tid]);
        vsh[tid] = __ldg(&vF[tid]);
    }
    ldgA(0, 0); ldgA(1, 1);
    __syncthreads();          // ush visible before stsA(0)
    stsA(0, 0);

    // ---- ldmatrix lane addressing (per mi) ----
    uint32_t arow_l = (uint32_t)(mw * 32 + (lane & 7) + ((lane >> 3) & 1) * 8);
    uint32_t slot16 = (uint32_t)((lane >> 4) << 4);
    uint32_t lrow[2], lxor[2];
#pragma unroll
    for (int mi = 0; mi < 2; mi++) {
        uint32_t r = arow_l + mi * 16;
        lrow[mi] = sb + AH_OFF + r * 64;
        lxor[mi] = ((r >> 1) & 3) << 4;
    }

    float acc[2][8][4];
#pragma unroll
    for (int mi = 0; mi < 2; mi++)
#pragma unroll
        for (int ni = 0; ni < 8; ni++)
#pragma unroll
            for (int j = 0; j < 4; j++) acc[mi][ni][j] = 0.f;

    // ---- mainloop over 8 K-chunks of 32 ----
#pragma unroll
    for (int c = 0; c < 8; c++) {
        if (c < 7) cpwait<1>(); else cpwait<0>();
        __syncthreads();
        if (c + 2 < 8) { issueB(c + 2); ldgA(c + 2, c & 1); }
        if (c + 1 < 8) stsA(c + 1, (c + 1) & 1);

        const uint4* Bsl = (const uint4*)(smem + B_OFF + (c % 3) * 16384);
        const uint32_t aoff = (uint32_t)((c & 1) * 8192);
#pragma unroll
        for (int t = 0; t < 2; t++) {
            uint32_t a[2][4];
#pragma unroll
            for (int mi = 0; mi < 2; mi++)
                ldsm4(a[mi], lrow[mi] + aoff + (((uint32_t)(32 * t) + slot16) ^ lxor[mi]));
            const uint4* bp = Bsl + (t * 16 + nw * 4) * 32 + lane;
#pragma unroll
            for (int p = 0; p < 4; p++) {
                uint4 bq = bp[p * 32];
#pragma unroll
                for (int mi = 0; mi < 2; mi++) {
                    mma16(acc[mi][2 * p],     a[mi][0], a[mi][1], a[mi][2], a[mi][3], bq.x, bq.y);
                    mma16(acc[mi][2 * p + 1], a[mi][0], a[mi][1], a[mi][2], a[mi][3], bq.z, bq.w);
                }
            }
        }
    }

    // ---- feature scores: sf[r] = sum_n tanh(z[r,n]) * v[n] ----
#pragma unroll
    for (int mi = 0; mi < 2; mi++) {
        float s0a = 0.f, s1a = 0.f;
#pragma unroll
        for (int ni = 0; ni < 8; ni++) {
            int n = nw * 64 + ni * 8 + cq * 2;
            float v0 = vsh[n], v1 = vsh[n + 1];
            s0a = fmaf(tanha(acc[mi][ni][0]), v0, s0a);
            s0a = fmaf(tanha(acc[mi][ni][1]), v1, s0a);
            s1a = fmaf(tanha(acc[mi][ni][2]), v0, s1a);
            s1a = fmaf(tanha(acc[mi][ni][3]), v1, s1a);
        }
        s0a += __shfl_xor_sync(0xFFFFFFFFu, s0a, 1);
        s0a += __shfl_xor_sync(0xFFFFFFFFu, s0a, 2);
        s1a += __shfl_xor_sync(0xFFFFFFFFu, s1a, 1);
        s1a += __shfl_xor_sync(0xFFFFFFFFu, s1a, 2);
        if (cq == 0) {
            int r = mw * 32 + mi * 16 + rq;
            scFr[nw * 128 + r] = s0a;
            scFr[nw * 128 + r + 8] = s1a;
        }
    }

    // ---- exact fp32 time scores: reduce over the 4 threads sharing a row ----
    sT += __shfl_xor_sync(0xFFFFFFFFu, sT, 1);
    sT += __shfl_xor_sync(0xFFFFFFFFu, sT, 2);
    if ((lane & 3) == 0) scT[arow] = sT;
    __syncthreads();
    if (tid < 128)
        scF[tid] = scFr[tid] + scFr[128 + tid] + scFr[256 + tid] + scFr[384 + tid];
    __syncthreads();

    // ---- split-softmax partials for both arrays (threads 0..255 active) ----
    float vv = 0.f, ee = 0.f;
    float* arr = (tid < 128) ? scT : scF;
    int i = tid & 127;
    if (tid < 256) {
        vv = arr[i];
        float m = vv;
#pragma unroll
        for (int off = 16; off; off >>= 1)
            m = fmaxf(m, __shfl_xor_sync(0xFFFFFFFFu, m, off));
        if (lane == 0) red[wid] = m;
    }
    __syncthreads();
    float M = 0.f;
    if (tid < 256) {
        M = (tid < 128)
            ? fmaxf(fmaxf(red[0], red[1]), fmaxf(red[2], red[3]))
            : fmaxf(fmaxf(red[4], red[5]), fmaxf(red[6], red[7]));
        ee = __expf(vv - M);
        float s = ee;
#pragma unroll
        for (int off = 16; off; off >>= 1)
            s += __shfl_xor_sync(0xFFFFFFFFu, s, off);
        if (lane == 0) red[16 + wid] = s;
    }
    __syncthreads();
    if (tid < 256) arr[i] = ee;
    __syncthreads();
    if (tid == 0)   { g_mT[tile] = M; g_sT[tile] = red[16] + red[17] + red[18] + red[19]; }
    if (tid == 128) { g_mF[tile] = M; g_sF[tile] = red[20] + red[21] + red[22] + red[23]; }

    // ---- exact fp32 weighted sums: re-read o from L2 via LDG.128 ----
    {
        int g = tid >> 6, hc = tid & 63;
        const float4* orow = (const float4*)obase + (size_t)(g * 16) * 64 + hc;
        float4 aT = {0.f, 0.f, 0.f, 0.f}, aF = {0.f, 0.f, 0.f, 0.f};
#pragma unroll 8
        for (int r = 0; r < 16; r++) {
            float4 ov = __ldg(orow + (size_t)r * 64);
            float wT = scT[g * 16 + r], wF = scF[g * 16 + r];
            aT.x = fmaf(wT, ov.x, aT.x); aT.y = fmaf(wT, ov.y, aT.y);
            aT.z = fmaf(wT, ov.z, aT.z); aT.w = fmaf(wT, ov.w, aT.w);
            aF.x = fmaf(wF, ov.x, aF.x); aF.y = fmaf(wF, ov.y, aF.y);
            aF.z = fmaf(wF, ov.z, aF.z); aF.w = fmaf(wF, ov.w, aF.w);
        }
        float* pTs = (float*)(smem + PTS_OFF);
        float* pFs = (float*)(smem + PFS_OFF);
        ((float4*)(pTs + g * 256))[hc] = aT;
        ((float4*)(pFs + g * 256))[hc] = aF;
    }
    __syncthreads();
    {
        float* pTs = (float*)(smem + PTS_OFF);
        float* pFs = (float*)(smem + PFS_OFF);
        if (tid < 256) {
            float a = 0.f;
#pragma unroll
            for (int g = 0; g < 8; g++) a += pTs[g * 256 + tid];
            g_pT[tile * HH + tid] = a;
        } else {
            int j = tid - 256;
            float a = 0.f;
#pragma unroll
            for (int g = 0; g < 8; g++) a += pFs[g * 256 + j];
            g_pF[tile * HH + j] = a;
        }
    }
}

// ---------------------------------------------------------------------------
// k_combine: exact split-softmax merge. grid = (BB, 2): y=0 time, y=1 feature.
// ---------------------------------------------------------------------------
__global__ void k_combine(float* __restrict__ out) {
    int b = blockIdx.x, h = threadIdx.x, which = blockIdx.y;
    const float* gm = which ? g_mF : g_mT;
    const float* gs = which ? g_sF : g_sT;
    const float* gp = which ? g_pF : g_pT;
    float M = -1e30f;
#pragma unroll
    for (int c = 0; c < 32; c++) M = fmaxf(M, gm[b * 32 + c]);
    float S = 0.f, oV = 0.f;
#pragma unroll
    for (int c = 0; c < 32; c++) {
        int t = b * 32 + c;
        float w = __expf(gm[t] - M);
        S = fmaf(w, gs[t], S);
        oV = fmaf(w, __ldg(&gp[t * HH + h]), oV);
    }
    out[b * 2 * HH + which * HH + h] = oV / S;
}

// ---------------------------------------------------------------------------
extern "C" void kernel_launch(void* const* d_in, const int* in_sizes, int n_in,
                              void* d_out, int out_size) {
    const float* o  = (const float*)d_in[0];
    const float* Wt = (const float*)d_in[1];
    const float* WF = (const float*)d_in[2];
    const float* vF = (const float*)d_in[3];
    float* out = (float*)d_out;

    cudaFuncSetAttribute(k_main, cudaFuncAttributeMaxDynamicSharedMemorySize, SMEM_TOTAL);

    k_init<<<1040, 512>>>(o, Wt, WF);
    k_main<<<NTILES, 512, SMEM_TOTAL>>>(o, vF);
    k_combine<<<dim3(BB, 2), HH>>>(out);
}

// round 9
// speedup vs baseline: 1.2639x; 1.0015x over previous
#include <cuda_runtime.h>
#include <cuda_fp16.h>
#include <math.h>
#include <stdint.h>

#define BB 64
#define SS 4096
#define HH 256
#define NTILES 2048            // BB*SS/128
#define GRID 152               // persistent CTAs (GB300: 152 SMs)

// ---------------- device-global scratch (no allocation allowed) -------------
__device__ float g_u[BB * HH];            // W_t @ o_last per batch (fp32)
__device__ uint4 g_Bh[16 * 16 * 32];      // W_F fp16 m16n8k16 B-fragment image (128 KB)
__device__ float g_pT[NTILES * HH];
__device__ float g_pF[NTILES * HH];
__device__ float g_mT[NTILES], g_sT[NTILES], g_mF[NTILES], g_sF[NTILES];

// ---------------- SMEM map (bytes) ------------------------------------------
#define AH_OFF    0            // 2 slots x 8192 (128 rows x 64B fp16)
#define B_OFF     16384        // 8 chunks x 16384 = 131072 (RESIDENT)
#define USH_OFF   147456       // 256 floats
#define VSH_OFF   148480       // 256 floats
#define SCT_OFF   149504       // 128 floats
#define SCF_OFF   150016       // 128 floats
#define SCFR_OFF  150528       // 4 x 128 floats = 2048
#define RED_OFF   152576       // 32 floats
#define PTS_OFF   152704       // 8 x 256 floats = 8192
#define PFS_OFF   160896       // 8 x 256 floats = 8192
#define SMEM_TOTAL 169088

// ---------------- helpers ----------------------------------------------------
__device__ __forceinline__ uint32_t packh2(float lo, float hi) {
    __half2 h = __floats2half2_rn(lo, hi);
    return *(uint32_t*)&h;
}
__device__ __forceinline__ float tanha(float x) {
    float y;
    asm("tanh.approx.f32 %0, %1;" : "=f"(y) : "f"(x));
    return y;
}
__device__ __forceinline__ void mma16(float* c, uint32_t a0, uint32_t a1,
                                      uint32_t a2, uint32_t a3,
                                      uint32_t b0, uint32_t b1) {
    asm volatile(
        "mma.sync.aligned.m16n8k16.row.col.f32.f16.f16.f32 "
        "{%0,%1,%2,%3}, {%4,%5,%6,%7}, {%8,%9}, {%0,%1,%2,%3};"
        : "+f"(c[0]), "+f"(c[1]), "+f"(c[2]), "+f"(c[3])
        : "r"(a0), "r"(a1), "r"(a2), "r"(a3), "r"(b0), "r"(b1));
}
__device__ __forceinline__ void ldsm4(uint32_t* a, uint32_t addr) {
    asm volatile("ldmatrix.sync.aligned.m8n8.x4.shared.b16 {%0,%1,%2,%3}, [%4];"
                 : "=r"(a[0]), "=r"(a[1]), "=r"(a[2]), "=r"(a[3]) : "r"(addr));
}
#define CP16(dst, src) \
    asm volatile("cp.async.cg.shared.global [%0], [%1], 16;" :: "r"(dst), "l"(src) : "memory")
#define CPCOMMIT() asm volatile("cp.async.commit_group;" ::: "memory")
template<int N> __device__ __forceinline__ void cpwait() {
    asm volatile("cp.async.wait_group %0;" :: "n"(N) : "memory");
}
__device__ __forceinline__ uint32_t s2u(const void* p) {
    uint32_t a;
    asm("{ .reg .u64 t; cvta.to.shared.u64 t, %1; cvt.u32.u64 %0, t; }" : "=r"(a) : "l"(p));
    return a;
}

// ---------------------------------------------------------------------------
// k_init: blocks 0..15 build the W_F fp16 B-fragment image (512 thr);
//         blocks 16..1039 compute u[b][h] = dot(W_t[h], o_last[b]) — one warp
//         per (b,h), coalesced LDG + shfl reduce.
// ---------------------------------------------------------------------------
__global__ void __launch_bounds__(512)
k_init(const float* __restrict__ o, const float* __restrict__ Wt,
       const float* __restrict__ WF) {
    int tid = threadIdx.x;
    if (blockIdx.x < 16) {
        int t = blockIdx.x;              // kstep 0..15
        int p = tid >> 5, l = tid & 31;
        int rq = l >> 2, cq = l & 3;
        int k0 = t * 16 + 2 * cq;
        int na = p * 16 + rq, nb = na + 8;
        uint4 q;
        q.x = packh2(WF[k0 * HH + na],       WF[(k0 + 1) * HH + na]);
        q.y = packh2(WF[(k0 + 8) * HH + na], WF[(k0 + 9) * HH + na]);
        q.z = packh2(WF[k0 * HH + nb],       WF[(k0 + 1) * HH + nb]);
        q.w = packh2(WF[(k0 + 8) * HH + nb], WF[(k0 + 9) * HH + nb]);
        g_Bh[(t * 16 + p) * 32 + l] = q;
    } else {
        int idx = (blockIdx.x - 16) * 16 + (tid >> 5);   // warp id 0..16383
        int lane = tid & 31;
        int b = idx >> 8, h = idx & 255;
        const float* wrow = Wt + h * HH;
        const float* olast = o + ((size_t)b * SS + (SS - 1)) * HH;
        float acc = 0.f;
#pragma unroll
        for (int j = 0; j < 8; j++) {
            int k = j * 32 + lane;
            acc = fmaf(__ldg(&wrow[k]), __ldg(&olast[k]), acc);
        }
#pragma unroll
        for (int off = 16; off; off >>= 1)
            acc += __shfl_xor_sync(0xFFFFFFFFu, acc, off);
        if (lane == 0) g_u[b * HH + h] = acc;
    }
}

// ---------------------------------------------------------------------------
// k_main: PERSISTENT. B image resident in SMEM; each CTA loops over tiles,
// prefetching the next tile's A chunks + u during the current epilogue.
// grid=GRID, block=512.
// ---------------------------------------------------------------------------
__global__ void __launch_bounds__(512, 1)
k_main(const float* __restrict__ o, const float* __restrict__ vF) {
    extern __shared__ __align__(16) char smem[];
    const uint32_t sb = s2u(smem);
    const int tid = threadIdx.x, lane = tid & 31, wid = tid >> 5;
    const int mw = wid & 3;   // M quarter (32 rows)
    const int nw = wid >> 2;  // N quarter (64 cols)
    const int rq = lane >> 2, cq = lane & 3;

    float* ush  = (float*)(smem + USH_OFF);
    float* vsh  = (float*)(smem + VSH_OFF);
    float* scT  = (float*)(smem + SCT_OFF);
    float* scF  = (float*)(smem + SCF_OFF);
    float* scFr = (float*)(smem + SCFR_OFF);
    float* red  = (float*)(smem + RED_OFF);

    // ---- load the FULL B fragment image once (128 KB, resident) ----
    {
        const uint4* bsrc = g_Bh;
#pragma unroll
        for (int j = 0; j < 16; j++) {
            int idx = tid + j * 512;
            CP16(sb + B_OFF + idx * 16, (const void*)(bsrc + idx));
        }
        CPCOMMIT();
    }
    if (tid < 256) vsh[tid] = __ldg(&vF[tid]);

    // ---- A STS addressing: row = tid>>2, q = tid&3 (8 cols of 32-col chunk) --
    const int arow = tid >> 2, q = tid & 3;
    const uint32_t axor = (uint32_t)(((arow >> 1) & 3) << 4);
    const uint32_t asts_off = AH_OFF + (uint32_t)arow * 64 + (((uint32_t)q * 16) ^ axor);

    // ---- ldmatrix lane addressing (per mi) ----
    uint32_t arow_l = (uint32_t)(mw * 32 + (lane & 7) + ((lane >> 3) & 1) * 8);
    uint32_t slot16 = (uint32_t)((lane >> 4) << 4);
    uint32_t lrow[2], lxor[2];
#pragma unroll
    for (int mi = 0; mi < 2; mi++) {
        uint32_t r = arow_l + mi * 16;
        lrow[mi] = sb + AH_OFF + r * 64;
        lxor[mi] = ((r >> 1) & 3) << 4;
    }

    float4 pf[2][2];
    float sT;

    cpwait<0>();
    __syncthreads();          // B image + vsh visible

    bool first = true;
#pragma unroll 1
    for (int tile = blockIdx.x; tile < NTILES; tile += GRID) {
        const int b = tile >> 5, s0 = (tile & 31) << 7;
        const float* obase = o + ((size_t)(b * SS + s0)) * HH;
        const float4* aldg = (const float4*)obase + (size_t)arow * 64 + q * 2;

        if (first) {           // uniform branch
            if (tid < 256) ush[tid] = __ldg(&g_u[b * HH + tid]);
            pf[0][0] = __ldg(aldg);     pf[0][1] = __ldg(aldg + 1);
            pf[1][0] = __ldg(aldg + 8); pf[1][1] = __ldg(aldg + 9);
            first = false;
            __syncthreads();
        }

        sT = 0.f;
        float acc[2][8][4];
#pragma unroll
        for (int mi = 0; mi < 2; mi++)
#pragma unroll
            for (int ni = 0; ni < 8; ni++)
#pragma unroll
                for (int j = 0; j < 4; j++) acc[mi][ni][j] = 0.f;

        // stsA: fold time-score FMAs, convert, store fp16 to AH slot
        auto stsA = [&](int c, int slot) {
            const float4 u0 = *(const float4*)(ush + c * 32 + q * 8);
            const float4 u1 = *(const float4*)(ush + c * 32 + q * 8 + 4);
            float4 a0 = pf[slot][0], a1 = pf[slot][1];
            sT = fmaf(a0.x, u0.x, sT); sT = fmaf(a0.y, u0.y, sT);
            sT = fmaf(a0.z, u0.z, sT); sT = fmaf(a0.w, u0.w, sT);
            sT = fmaf(a1.x, u1.x, sT); sT = fmaf(a1.y, u1.y, sT);
            sT = fmaf(a1.z, u1.z, sT); sT = fmaf(a1.w, u1.w, sT);
            uint4 qq;
            qq.x = packh2(a0.x, a0.y); qq.y = packh2(a0.z, a0.w);
            qq.z = packh2(a1.x, a1.y); qq.w = packh2(a1.z, a1.w);
            *(uint4*)(smem + (slot) * 8192 + asts_off) = qq;
        };

        stsA(0, 0);

        // ---- mainloop over 8 K-chunks of 32 (B resident, no waits) ----
#pragma unroll
        for (int c = 0; c < 8; c++) {
            __syncthreads();
            if (c + 1 < 8) stsA(c + 1, (c + 1) & 1);
            if (c + 2 < 8) {
                pf[c & 1][0] = __ldg(aldg + (c + 2) * 8);
                pf[c & 1][1] = __ldg(aldg + (c + 2) * 8 + 1);
            }
            const uint4* Bsl = (const uint4*)(smem + B_OFF + c * 16384);
            const uint32_t aoff = (uint32_t)((c & 1) * 8192);
#pragma unroll
            for (int t = 0; t < 2; t++) {
                uint32_t a[2][4];
#pragma unroll
                for (int mi = 0; mi < 2; mi++)
                    ldsm4(a[mi], lrow[mi] + aoff + (((uint32_t)(32 * t) + slot16) ^ lxor[mi]));
                const uint4* bp = Bsl + (t * 16 + nw * 4) * 32 + lane;
#pragma unroll
                for (int p = 0; p < 4; p++) {
                    uint4 bq = bp[p * 32];
#pragma unroll
                    for (int mi = 0; mi < 2; mi++) {
                        mma16(acc[mi][2 * p],     a[mi][0], a[mi][1], a[mi][2], a[mi][3], bq.x, bq.y);
                        mma16(acc[mi][2 * p + 1], a[mi][0], a[mi][1], a[mi][2], a[mi][3], bq.z, bq.w);
                    }
                }
            }
        }

        // ---- prefetch NEXT tile's A chunks 0/1 + u during epilogue ----
        {
            const int ntile = tile + GRID;
            if (ntile < NTILES) {
                const int nb2 = ntile >> 5, ns0 = (ntile & 31) << 7;
                const float4* naldg = (const float4*)(o + ((size_t)(nb2 * SS + ns0)) * HH)
                                      + (size_t)arow * 64 + q * 2;
                if (tid < 256) ush[tid] = __ldg(&g_u[nb2 * HH + tid]);
                pf[0][0] = __ldg(naldg);     pf[0][1] = __ldg(naldg + 1);
                pf[1][0] = __ldg(naldg + 8); pf[1][1] = __ldg(naldg + 9);
            }
        }

        // ---- feature scores: sf[r] = sum_n tanh(z[r,n]) * v[n] ----
#pragma unroll
        for (int mi = 0; mi < 2; mi++) {
            float s0a = 0.f, s1a = 0.f;
#pragma unroll
            for (int ni = 0; ni < 8; ni++) {
                int n = nw * 64 + ni * 8 + cq * 2;
                float v0 = vsh[n], v1 = vsh[n + 1];
                s0a = fmaf(tanha(acc[mi][ni][0]), v0, s0a);
                s0a = fmaf(tanha(acc[mi][ni][1]), v1, s0a);
                s1a = fmaf(tanha(acc[mi][ni][2]), v0, s1a);
                s1a = fmaf(tanha(acc[mi][ni][3]), v1, s1a);
            }
            s0a += __shfl_xor_sync(0xFFFFFFFFu, s0a, 1);
            s0a += __shfl_xor_sync(0xFFFFFFFFu, s0a, 2);
            s1a += __shfl_xor_sync(0xFFFFFFFFu, s1a, 1);
            s1a += __shfl_xor_sync(0xFFFFFFFFu, s1a, 2);
            if (cq == 0) {
                int r = mw * 32 + mi * 16 + rq;
                scFr[nw * 128 + r] = s0a;
                scFr[nw * 128 + r + 8] = s1a;
            }
        }

        // ---- exact fp32 time scores: reduce 4 threads sharing a row ----
        sT += __shfl_xor_sync(0xFFFFFFFFu, sT, 1);
        sT += __shfl_xor_sync(0xFFFFFFFFu, sT, 2);
        if ((lane & 3) == 0) scT[arow] = sT;
        __syncthreads();
        if (tid < 128)
            scF[tid] = scFr[tid] + scFr[128 + tid] + scFr[256 + tid] + scFr[384 + tid];
        __syncthreads();

        // ---- split-softmax partials (threads 0..255) ----
        float vv = 0.f, ee = 0.f;
        float* arr = (tid < 128) ? scT : scF;
        int i = tid & 127;
        if (tid < 256) {
            vv = arr[i];
            float m = vv;
#pragma unroll
            for (int off = 16; off; off >>= 1)
                m = fmaxf(m, __shfl_xor_sync(0xFFFFFFFFu, m, off));
            if (lane == 0) red[wid] = m;
        }
        __syncthreads();
        float M = 0.f;
        if (tid < 256) {
            M = (tid < 128)
                ? fmaxf(fmaxf(red[0], red[1]), fmaxf(red[2], red[3]))
                : fmaxf(fmaxf(red[4], red[5]), fmaxf(red[6], red[7]));
            ee = __expf(vv - M);
            float s = ee;
#pragma unroll
            for (int off = 16; off; off >>= 1)
                s += __shfl_xor_sync(0xFFFFFFFFu, s, off);
            if (lane == 0) red[16 + wid] = s;
        }
        __syncthreads();
        if (tid < 256) arr[i] = ee;
        __syncthreads();
        if (tid == 0)   { g_mT[tile] = M; g_sT[tile] = red[16] + red[17] + red[18] + red[19]; }
        if (tid == 128) { g_mF[tile] = M; g_sF[tile] = red[20] + red[21] + red[22] + red[23]; }

        // ---- exact fp32 weighted sums: re-read o (L2-hot) via LDG.128 ----
        {
            int g = tid >> 6, hc = tid & 63;
            const float4* orow = (const float4*)obase + (size_t)(g * 16) * 64 + hc;
            float4 aT = {0.f, 0.f, 0.f, 0.f}, aF = {0.f, 0.f, 0.f, 0.f};
#pragma unroll 8
            for (int r = 0; r < 16; r++) {
                float4 ov = __ldg(orow + (size_t)r * 64);
                float wT = scT[g * 16 + r], wF = scF[g * 16 + r];
                aT.x = fmaf(wT, ov.x, aT.x); aT.y = fmaf(wT, ov.y, aT.y);
                aT.z = fmaf(wT, ov.z, aT.z); aT.w = fmaf(wT, ov.w, aT.w);
                aF.x = fmaf(wF, ov.x, aF.x); aF.y = fmaf(wF, ov.y, aF.y);
                aF.z = fmaf(wF, ov.z, aF.z); aF.w = fmaf(wF, ov.w, aF.w);
            }
            float* pTs = (float*)(smem + PTS_OFF);
            float* pFs = (float*)(smem + PFS_OFF);
            ((float4*)(pTs + g * 256))[hc] = aT;
            ((float4*)(pFs + g * 256))[hc] = aF;
        }
        __syncthreads();
        {
            float* pTs = (float*)(smem + PTS_OFF);
            float* pFs = (float*)(smem + PFS_OFF);
            if (tid < 256) {
                float a = 0.f;
#pragma unroll
                for (int g = 0; g < 8; g++) a += pTs[g * 256 + tid];
                g_pT[tile * HH + tid] = a;
            } else {
                int j = tid - 256;
                float a = 0.f;
#pragma unroll
                for (int g = 0; g < 8; g++) a += pFs[g * 256 + j];
                g_pF[tile * HH + j] = a;
            }
        }
        __syncthreads();       // PTS/PFS reads done before next tile reuses smem
    }
}

// ---------------------------------------------------------------------------
// k_combine: exact split-softmax merge. grid = (BB, 2): y=0 time, y=1 feature.
// ---------------------------------------------------------------------------
__global__ void k_combine(float* __restrict__ out) {
    int b = blockIdx.x, h = threadIdx.x, which = blockIdx.y;
    const float* gm = which ? g_mF : g_mT;
    const float* gs = which ? g_sF : g_sT;
    const float* gp = which ? g_pF : g_pT;
    float M = -1e30f;
#pragma unroll
    for (int c = 0; c < 32; c++) M = fmaxf(M, gm[b * 32 + c]);
    float S = 0.f, oV = 0.f;
#pragma unroll
    for (int c = 0; c < 32; c++) {
        int t = b * 32 + c;
        float w = __expf(gm[t] - M);
        S = fmaf(w, gs[t], S);
        oV = fmaf(w, __ldg(&gp[t * HH + h]), oV);
    }
    out[b * 2 * HH + which * HH + h] = oV / S;
}

// ---------------------------------------------------------------------------
extern "C" void kernel_launch(void* const* d_in, const int* in_sizes, int n_in,
                              void* d_out, int out_size) {
    const float* o  = (const float*)d_in[0];
    const float* Wt = (const float*)d_in[1];
    const float* WF = (const float*)d_in[2];
    const float* vF = (const float*)d_in[3];
    float* out = (float*)d_out;

    cudaFuncSetAttribute(k_main, cudaFuncAttributeMaxDynamicSharedMemorySize, SMEM_TOTAL);

    k_init<<<1040, 512>>>(o, Wt, WF);
    k_main<<<GRID, 512, SMEM_TOTAL>>>(o, vF);
    k_combine<<<dim3(BB, 2), HH>>>(out);
}

// round 10
// speedup vs baseline: 1.3148x; 1.0402x over previous
#include <cuda_runtime.h>
#include <cuda_fp16.h>
#include <math.h>
#include <stdint.h>

#define BB 64
#define SS 4096
#define HH 256
#define NTILES 4096            // BB*SS/64  (M=64 tiles)

// ---------------- device-global scratch (no allocation allowed) -------------
__device__ float g_u[BB * HH];            // W_t @ o_last per batch (fp32)
__device__ uint4 g_Bh[16 * 16 * 32];      // W_F fp16 m16n8k16 B-fragment image (128 KB)
__device__ float g_pT[NTILES * HH];
__device__ float g_pF[NTILES * HH];
__device__ float g_mT[NTILES], g_sT[NTILES], g_mF[NTILES], g_sF[NTILES];
__device__ int   g_dummy;

// ---------------- SMEM map (bytes), 69248 total -> 2 CTAs/SM ----------------
#define AH_OFF    0            // 2 slots x 4096 (64 rows x 64B fp16)
#define B_OFF     8192         // 3 slots x 16384 = 49152 (fp16 fragments)
#define USH_OFF   57344        // 256 floats
#define VSH_OFF   58368        // 256 floats
#define SCT_OFF   59392        // 64 floats
#define SCF_OFF   59648        // 64 floats
#define SCFR_OFF  59904        // 4 x 64 floats = 1024
#define RED_OFF   60928        // 32 floats
#define PTS_OFF   61056        // 4 x 256 floats = 4096
#define PFS_OFF   65152        // 4 x 256 floats = 4096
#define SMEM_TOTAL 69248

// ---------------- helpers ----------------------------------------------------
__device__ __forceinline__ uint32_t packh2(float lo, float hi) {
    __half2 h = __floats2half2_rn(lo, hi);
    return *(uint32_t*)&h;
}
__device__ __forceinline__ float tanha(float x) {
    float y;
    asm("tanh.approx.f32 %0, %1;" : "=f"(y) : "f"(x));
    return y;
}
__device__ __forceinline__ void mma16(float* c, uint32_t a0, uint32_t a1,
                                      uint32_t a2, uint32_t a3,
                                      uint32_t b0, uint32_t b1) {
    asm volatile(
        "mma.sync.aligned.m16n8k16.row.col.f32.f16.f16.f32 "
        "{%0,%1,%2,%3}, {%4,%5,%6,%7}, {%8,%9}, {%0,%1,%2,%3};"
        : "+f"(c[0]), "+f"(c[1]), "+f"(c[2]), "+f"(c[3])
        : "r"(a0), "r"(a1), "r"(a2), "r"(a3), "r"(b0), "r"(b1));
}
__device__ __forceinline__ void ldsm4(uint32_t* a, uint32_t addr) {
    asm volatile("ldmatrix.sync.aligned.m8n8.x4.shared.b16 {%0,%1,%2,%3}, [%4];"
                 : "=r"(a[0]), "=r"(a[1]), "=r"(a[2]), "=r"(a[3]) : "r"(addr));
}
#define CP16(dst, src) \
    asm volatile("cp.async.cg.shared.global [%0], [%1], 16;" :: "r"(dst), "l"(src) : "memory")
#define CPCOMMIT() asm volatile("cp.async.commit_group;" ::: "memory")
template<int N> __device__ __forceinline__ void cpwait() {
    asm volatile("cp.async.wait_group %0;" :: "n"(N) : "memory");
}
__device__ __forceinline__ uint32_t s2u(const void* p) {
    uint32_t a;
    asm("{ .reg .u64 t; cvta.to.shared.u64 t, %1; cvt.u32.u64 %0, t; }" : "=r"(a) : "l"(p));
    return a;
}

// ---------------------------------------------------------------------------
// k_init: blocks 0..15 build the W_F fp16 B-fragment image;
//         blocks 16..1039 compute u[b][h] via coalesced warp-dot.
// ---------------------------------------------------------------------------
__global__ void __launch_bounds__(512)
k_init(const float* __restrict__ o, const float* __restrict__ Wt,
       const float* __restrict__ WF) {
    int tid = threadIdx.x;
    if (blockIdx.x < 16) {
        int t = blockIdx.x;
        int p = tid >> 5, l = tid & 31;
        int rq = l >> 2, cq = l & 3;
        int k0 = t * 16 + 2 * cq;
        int na = p * 16 + rq, nb = na + 8;
        uint4 q;
        q.x = packh2(WF[k0 * HH + na],       WF[(k0 + 1) * HH + na]);
        q.y = packh2(WF[(k0 + 8) * HH + na], WF[(k0 + 9) * HH + na]);
        q.z = packh2(WF[k0 * HH + nb],       WF[(k0 + 1) * HH + nb]);
        q.w = packh2(WF[(k0 + 8) * HH + nb], WF[(k0 + 9) * HH + nb]);
        g_Bh[(t * 16 + p) * 32 + l] = q;
    } else {
        int idx = (blockIdx.x - 16) * 16 + (tid >> 5);
        int lane = tid & 31;
        int b = idx >> 8, h = idx & 255;
        const float* wrow = Wt + h * HH;
        const float* olast = o + ((size_t)b * SS + (SS - 1)) * HH;
        float acc = 0.f;
#pragma unroll
        for (int j = 0; j < 8; j++) {
            int k = j * 32 + lane;
            acc = fmaf(__ldg(&wrow[k]), __ldg(&olast[k]), acc);
        }
#pragma unroll
        for (int off = 16; off; off >>= 1)
            acc += __shfl_xor_sync(0xFFFFFFFFu, acc, off);
        if (lane == 0) g_u[b * HH + h] = acc;
    }
}

// ---------------------------------------------------------------------------
// k_main: M=64 tile, 256 threads, 2 CTAs/SM. Fused feature GEMM (fp16 mma) +
//         exact fp32 time scores + tanh·v_F + split-softmax partials + exact
//         fp32 weighted sums. grid=4096, block=256.
// ---------------------------------------------------------------------------
__global__ void __launch_bounds__(256, 2)
k_main(const float* __restrict__ o, const float* __restrict__ vF) {
    extern __shared__ __align__(16) char smem[];
    const uint32_t sb = s2u(smem);
    const int tid = threadIdx.x, lane = tid & 31, wid = tid >> 5;
    const int tile = blockIdx.x;
    const int b = tile >> 6, s0 = (tile & 63) << 6;
    const int mw = wid & 1;   // M half (32 rows)
    const int nw = wid >> 1;  // N quarter (64 cols)
    const int rq = lane >> 2, cq = lane & 3;

    float* ush  = (float*)(smem + USH_OFF);
    float* vsh  = (float*)(smem + VSH_OFF);
    float* scT  = (float*)(smem + SCT_OFF);
    float* scF  = (float*)(smem + SCF_OFF);
    float* scFr = (float*)(smem + SCFR_OFF);
    float* red  = (float*)(smem + RED_OFF);

    const float* obase = o + ((size_t)(b * SS + s0)) * HH;

    // ---- B chunk issue via cp.async (fragment image, 16 KB/chunk) ----
    auto issueB = [&](int c) {
        uint32_t bdst = sb + B_OFF + (c % 3) * 16384;
        const uint4* bsrc = g_Bh + c * 1024;
#pragma unroll
        for (int j = 0; j < 4; j++) {
            int idx = tid + j * 256;
            CP16(bdst + idx * 16, (const void*)(bsrc + idx));
        }
        CPCOMMIT();
    };

    // ---- A prefetch (LDG->fp32 regs), fold time-score FMAs, fp16 STS ----
    // thread: row = tid>>2 (0..63), q = tid&3 (8 cols of each 32-col chunk)
    const int arow = tid >> 2, q = tid & 3;
    const float4* aldg = (const float4*)obase + (size_t)arow * 64 + q * 2;
    const uint32_t axor = (uint32_t)(((arow >> 1) & 3) << 4);
    const uint32_t asts_off = AH_OFF + (uint32_t)arow * 64 + (((uint32_t)q * 16) ^ axor);

    float4 pf[2][2];
    float sT = 0.f;
    auto ldgA = [&](int c, int slot) {
        pf[slot][0] = __ldg(aldg + c * 8);
        pf[slot][1] = __ldg(aldg + c * 8 + 1);
    };
    auto stsA = [&](int c, int slot) {
        const float4 u0 = *(const float4*)(ush + c * 32 + q * 8);
        const float4 u1 = *(const float4*)(ush + c * 32 + q * 8 + 4);
        float4 a0 = pf[slot][0], a1 = pf[slot][1];
        sT = fmaf(a0.x, u0.x, sT); sT = fmaf(a0.y, u0.y, sT);
        sT = fmaf(a0.z, u0.z, sT); sT = fmaf(a0.w, u0.w, sT);
        sT = fmaf(a1.x, u1.x, sT); sT = fmaf(a1.y, u1.y, sT);
        sT = fmaf(a1.z, u1.z, sT); sT = fmaf(a1.w, u1.w, sT);
        uint4 qq;
        qq.x = packh2(a0.x, a0.y); qq.y = packh2(a0.z, a0.w);
        qq.z = packh2(a1.x, a1.y); qq.w = packh2(a1.z, a1.w);
        *(uint4*)(smem + slot * 4096 + asts_off) = qq;
    };

    // ---- prologue ----
    issueB(0); issueB(1);
    ush[tid] = __ldg(&g_u[b * HH + tid]);
    vsh[tid] = __ldg(&vF[tid]);
    ldgA(0, 0); ldgA(1, 1);
    __syncthreads();          // ush visible before stsA(0)
    stsA(0, 0);

    // ---- ldmatrix lane addressing (per mi) ----
    uint32_t arow_l = (uint32_t)(mw * 32 + (lane & 7) + ((lane >> 3) & 1) * 8);
    uint32_t slot16 = (uint32_t)((lane >> 4) << 4);
    uint32_t lrow[2], lxor[2];
#pragma unroll
    for (int mi = 0; mi < 2; mi++) {
        uint32_t r = arow_l + mi * 16;
        lrow[mi] = sb + AH_OFF + r * 64;
        lxor[mi] = ((r >> 1) & 3) << 4;
    }

    float acc[2][8][4];
#pragma unroll
    for (int mi = 0; mi < 2; mi++)
#pragma unroll
        for (int ni = 0; ni < 8; ni++)
#pragma unroll
            for (int j = 0; j < 4; j++) acc[mi][ni][j] = 0.f;

    // ---- mainloop over 8 K-chunks of 32 ----
#pragma unroll
    for (int c = 0; c < 8; c++) {
        if (c < 7) cpwait<1>(); else cpwait<0>();
        __syncthreads();
        if (c + 2 < 8) { issueB(c + 2); ldgA(c + 2, c & 1); }
        if (c + 1 < 8) stsA(c + 1, (c + 1) & 1);

        const uint4* Bsl = (const uint4*)(smem + B_OFF + (c % 3) * 16384);
        const uint32_t aoff = (uint32_t)((c & 1) * 4096);
#pragma unroll
        for (int t = 0; t < 2; t++) {
            uint32_t a[2][4];
#pragma unroll
            for (int mi = 0; mi < 2; mi++)
                ldsm4(a[mi], lrow[mi] + aoff + (((uint32_t)(32 * t) + slot16) ^ lxor[mi]));
            const uint4* bp = Bsl + (t * 16 + nw * 4) * 32 + lane;
#pragma unroll
            for (int p = 0; p < 4; p++) {
                uint4 bq = bp[p * 32];
#pragma unroll
                for (int mi = 0; mi < 2; mi++) {
                    mma16(acc[mi][2 * p],     a[mi][0], a[mi][1], a[mi][2], a[mi][3], bq.x, bq.y);
                    mma16(acc[mi][2 * p + 1], a[mi][0], a[mi][1], a[mi][2], a[mi][3], bq.z, bq.w);
                }
            }
        }
    }

    // ---- feature scores: sf[r] = sum_n tanh(z[r,n]) * v[n] ----
#pragma unroll
    for (int mi = 0; mi < 2; mi++) {
        float s0a = 0.f, s1a = 0.f;
#pragma unroll
        for (int ni = 0; ni < 8; ni++) {
            int n = nw * 64 + ni * 8 + cq * 2;
            float v0 = vsh[n], v1 = vsh[n + 1];
            s0a = fmaf(tanha(acc[mi][ni][0]), v0, s0a);
            s0a = fmaf(tanha(acc[mi][ni][1]), v1, s0a);
            s1a = fmaf(tanha(acc[mi][ni][2]), v0, s1a);
            s1a = fmaf(tanha(acc[mi][ni][3]), v1, s1a);
        }
        s0a += __shfl_xor_sync(0xFFFFFFFFu, s0a, 1);
        s0a += __shfl_xor_sync(0xFFFFFFFFu, s0a, 2);
        s1a += __shfl_xor_sync(0xFFFFFFFFu, s1a, 1);
        s1a += __shfl_xor_sync(0xFFFFFFFFu, s1a, 2);
        if (cq == 0) {
            int r = mw * 32 + mi * 16 + rq;
            scFr[nw * 64 + r] = s0a;
            scFr[nw * 64 + r + 8] = s1a;
        }
    }

    // ---- exact fp32 time scores: reduce 4 threads sharing a row ----
    sT += __shfl_xor_sync(0xFFFFFFFFu, sT, 1);
    sT += __shfl_xor_sync(0xFFFFFFFFu, sT, 2);
    if ((lane & 3) == 0) scT[arow] = sT;
    __syncthreads();
    if (tid < 64)
        scF[tid] = scFr[tid] + scFr[64 + tid] + scFr[128 + tid] + scFr[192 + tid];
    __syncthreads();

    // ---- split-softmax partials (threads 0..127: warps 0-1 T, 2-3 F) ----
    float vv = 0.f, ee = 0.f;
    float* arr = (tid < 64) ? scT : scF;
    int i = tid & 63;
    if (tid < 128) {
        vv = arr[i];
        float m = vv;
#pragma unroll
        for (int off = 16; off; off >>= 1)
            m = fmaxf(m, __shfl_xor_sync(0xFFFFFFFFu, m, off));
        if (lane == 0) red[wid] = m;
    }
    __syncthreads();
    float M = 0.f;
    if (tid < 128) {
        M = (tid < 64) ? fmaxf(red[0], red[1]) : fmaxf(red[2], red[3]);
        ee = __expf(vv - M);
        float s = ee;
#pragma unroll
        for (int off = 16; off; off >>= 1)
            s += __shfl_xor_sync(0xFFFFFFFFu, s, off);
        if (lane == 0) red[16 + wid] = s;
    }
    __syncthreads();
    if (tid < 128) arr[i] = ee;
    __syncthreads();
    if (tid == 0)  { g_mT[tile] = M; g_sT[tile] = red[16] + red[17]; }
    if (tid == 64) { g_mF[tile] = M; g_sF[tile] = red[18] + red[19]; }

    // ---- exact fp32 weighted sums: re-read o (L2-hot) via LDG.128 ----
    {
        int g = tid >> 6, hc = tid & 63;
        const float4* orow = (const float4*)obase + (size_t)(g * 16) * 64 + hc;
        float4 aT = {0.f, 0.f, 0.f, 0.f}, aF = {0.f, 0.f, 0.f, 0.f};
#pragma unroll 8
        for (int r = 0; r < 16; r++) {
            float4 ov = __ldg(orow + (size_t)r * 64);
            float wT = scT[g * 16 + r], wF = scF[g * 16 + r];
            aT.x = fmaf(wT, ov.x, aT.x); aT.y = fmaf(wT, ov.y, aT.y);
            aT.z = fmaf(wT, ov.z, aT.z); aT.w = fmaf(wT, ov.w, aT.w);
            aF.x = fmaf(wF, ov.x, aF.x); aF.y = fmaf(wF, ov.y, aF.y);
            aF.z = fmaf(wF, ov.z, aF.z); aF.w = fmaf(wF, ov.w, aF.w);
        }
        float* pTs = (float*)(smem + PTS_OFF);
        float* pFs = (float*)(smem + PFS_OFF);
        ((float4*)(pTs + g * 256))[hc] = aT;
        ((float4*)(pFs + g * 256))[hc] = aF;
    }
    __syncthreads();
    {
        float* pTs = (float*)(smem + PTS_OFF);
        float* pFs = (float*)(smem + PFS_OFF);
        float a = pTs[tid] + pTs[256 + tid] + pTs[512 + tid] + pTs[768 + tid];
        float f = pFs[tid] + pFs[256 + tid] + pFs[512 + tid] + pFs[768 + tid];
        g_pT[tile * HH + tid] = a;
        g_pF[tile * HH + tid] = f;
    }
}

// ---------------------------------------------------------------------------
// k_combine: exact split-softmax merge over 64 s-tiles per batch.
// grid = (BB, 2): y=0 time, y=1 feature.
// ---------------------------------------------------------------------------
__global__ void k_combine(float* __restrict__ out) {
    int b = blockIdx.x, h = threadIdx.x, which = blockIdx.y;
    const float* gm = which ? g_mF : g_mT;
    const float* gs = which ? g_sF : g_sT;
    const float* gp = which ? g_pF : g_pT;
    float M = -1e30f;
#pragma unroll
    for (int c = 0; c < 64; c++) M = fmaxf(M, gm[b * 64 + c]);
    float S = 0.f, oV = 0.f;
#pragma unroll 8
    for (int c = 0; c < 64; c++) {
        int t = b * 64 + c;
        float w = __expf(gm[t] - M);
        S = fmaf(w, gs[t], S);
        oV = fmaf(w, __ldg(&gp[t * HH + h]), oV);
    }
    out[b * 2 * HH + which * HH + h] = oV / S;
}

// k_dummy: 4th launch so ncu's "-s 5 -c 1" lands on k_main (index 5 ≡ 1 mod 4)
__global__ void k_dummy() { g_dummy = 1; }

// ---------------------------------------------------------------------------
extern "C" void kernel_launch(void* const* d_in, const int* in_sizes, int n_in,
                              void* d_out, int out_size) {
    const float* o  = (const float*)d_in[0];
    const float* Wt = (const float*)d_in[1];
    const float* WF = (const float*)d_in[2];
    const float* vF = (const float*)d_in[3];
    float* out = (float*)d_out;

    cudaFuncSetAttribute(k_main, cudaFuncAttributeMaxDynamicSharedMemorySize, SMEM_TOTAL);

    k_init<<<1040, 512>>>(o, Wt, WF);
    k_main<<<NTILES, 256, SMEM_TOTAL>>>(o, vF);
    k_combine<<<dim3(BB, 2), HH>>>(out);
    k_dummy<<<1, 1>>>();
}

// round 11
// speedup vs baseline: 1.4338x; 1.0905x over previous
#include <cuda_runtime.h>
#include <cuda_fp16.h>
#include <math.h>
#include <stdint.h>

#define BB 64
#define SS 4096
#define HH 256
#define NTILES 4096            // BB*SS/64  (M=64 tiles)

// ---------------- device-global scratch (no allocation allowed) -------------
__device__ float g_u[BB * HH];            // W_t @ o_last per batch (fp32)
__device__ uint4 g_Bh[16 * 16 * 32];      // W_F fp16 m16n8k16 B-fragment image (128 KB)
__device__ float g_pT[NTILES * HH];
__device__ float g_pF[NTILES * HH];
__device__ float g_mT[NTILES], g_sT[NTILES], g_mF[NTILES], g_sF[NTILES];

// ---------------- SMEM map (bytes), 69248 total -> 2 CTAs/SM ----------------
#define AH_OFF    0            // 2 slots x 4096 (64 rows x 64B fp16)
#define B_OFF     8192         // 3 slots x 16384 = 49152 (fp16 fragments)
#define USH_OFF   57344        // 256 floats
#define VSH_OFF   58368        // 256 floats
#define SCT_OFF   59392        // 64 floats
#define SCF_OFF   59648        // 64 floats
#define SCFR_OFF  59904        // 4 x 64 floats = 1024
#define RED_OFF   60928        // 32 floats
#define PTS_OFF   61056        // 4 x 256 floats = 4096
#define PFS_OFF   65152        // 4 x 256 floats = 4096
#define SMEM_TOTAL 69248

// ---------------- helpers ----------------------------------------------------
__device__ __forceinline__ uint32_t packh2(float lo, float hi) {
    __half2 h = __floats2half2_rn(lo, hi);
    return *(uint32_t*)&h;
}
__device__ __forceinline__ float tanha(float x) {
    float y;
    asm("tanh.approx.f32 %0, %1;" : "=f"(y) : "f"(x));
    return y;
}
__device__ __forceinline__ void mma16(float* c, uint32_t a0, uint32_t a1,
                                      uint32_t a2, uint32_t a3,
                                      uint32_t b0, uint32_t b1) {
    asm volatile(
        "mma.sync.aligned.m16n8k16.row.col.f32.f16.f16.f32 "
        "{%0,%1,%2,%3}, {%4,%5,%6,%7}, {%8,%9}, {%0,%1,%2,%3};"
        : "+f"(c[0]), "+f"(c[1]), "+f"(c[2]), "+f"(c[3])
        : "r"(a0), "r"(a1), "r"(a2), "r"(a3), "r"(b0), "r"(b1));
}
__device__ __forceinline__ void ldsm4(uint32_t* a, uint32_t addr) {
    asm volatile("ldmatrix.sync.aligned.m8n8.x4.shared.b16 {%0,%1,%2,%3}, [%4];"
                 : "=r"(a[0]), "=r"(a[1]), "=r"(a[2]), "=r"(a[3]) : "r"(addr));
}
#define CP16(dst, src) \
    asm volatile("cp.async.cg.shared.global [%0], [%1], 16;" :: "r"(dst), "l"(src) : "memory")
#define CPCOMMIT() asm volatile("cp.async.commit_group;" ::: "memory")
template<int N> __device__ __forceinline__ void cpwait() {
    asm volatile("cp.async.wait_group %0;" :: "n"(N) : "memory");
}
__device__ __forceinline__ uint32_t s2u(const void* p) {
    uint32_t a;
    asm("{ .reg .u64 t; cvta.to.shared.u64 t, %1; cvt.u32.u64 %0, t; }" : "=r"(a) : "l"(p));
    return a;
}

// ---------------------------------------------------------------------------
// k_init: blocks 0..15 build the W_F fp16 B-fragment image;
//         blocks 16..1039 compute u[b][h] via coalesced warp-dot.
// ---------------------------------------------------------------------------
__global__ void __launch_bounds__(512)
k_init(const float* __restrict__ o, const float* __restrict__ Wt,
       const float* __restrict__ WF) {
    int tid = threadIdx.x;
    if (blockIdx.x < 16) {
        int t = blockIdx.x;
        int p = tid >> 5, l = tid & 31;
        int rq = l >> 2, cq = l & 3;
        int k0 = t * 16 + 2 * cq;
        int na = p * 16 + rq, nb = na + 8;
        uint4 q;
        q.x = packh2(WF[k0 * HH + na],       WF[(k0 + 1) * HH + na]);
        q.y = packh2(WF[(k0 + 8) * HH + na], WF[(k0 + 9) * HH + na]);
        q.z = packh2(WF[k0 * HH + nb],       WF[(k0 + 1) * HH + nb]);
        q.w = packh2(WF[(k0 + 8) * HH + nb], WF[(k0 + 9) * HH + nb]);
        g_Bh[(t * 16 + p) * 32 + l] = q;
    } else {
        int idx = (blockIdx.x - 16) * 16 + (tid >> 5);
        int lane = tid & 31;
        int b = idx >> 8, h = idx & 255;
        const float* wrow = Wt + h * HH;
        const float* olast = o + ((size_t)b * SS + (SS - 1)) * HH;
        float acc = 0.f;
#pragma unroll
        for (int j = 0; j < 8; j++) {
            int k = j * 32 + lane;
            acc = fmaf(__ldg(&wrow[k]), __ldg(&olast[k]), acc);
        }
#pragma unroll
        for (int off = 16; off; off >>= 1)
            acc += __shfl_xor_sync(0xFFFFFFFFu, acc, off);
        if (lane == 0) g_u[b * HH + h] = acc;
    }
}

// ---------------------------------------------------------------------------
// k_main: M=64 tile, 256 threads, 2 CTAs/SM. Fused feature GEMM (fp16 mma) +
//         exact fp32 time scores + tanh·v_F + split-softmax partials + exact
//         fp32 weighted sums. grid=4096, block=256.  [round-10, unchanged]
// ---------------------------------------------------------------------------
__global__ void __launch_bounds__(256, 2)
k_main(const float* __restrict__ o, const float* __restrict__ vF) {
    extern __shared__ __align__(16) char smem[];
    const uint32_t sb = s2u(smem);
    const int tid = threadIdx.x, lane = tid & 31, wid = tid >> 5;
    const int tile = blockIdx.x;
    const int b = tile >> 6, s0 = (tile & 63) << 6;
    const int mw = wid & 1;   // M half (32 rows)
    const int nw = wid >> 1;  // N quarter (64 cols)
    const int rq = lane >> 2, cq = lane & 3;

    float* ush  = (float*)(smem + USH_OFF);
    float* vsh  = (float*)(smem + VSH_OFF);
    float* scT  = (float*)(smem + SCT_OFF);
    float* scF  = (float*)(smem + SCF_OFF);
    float* scFr = (float*)(smem + SCFR_OFF);
    float* red  = (float*)(smem + RED_OFF);

    const float* obase = o + ((size_t)(b * SS + s0)) * HH;

    auto issueB = [&](int c) {
        uint32_t bdst = sb + B_OFF + (c % 3) * 16384;
        const uint4* bsrc = g_Bh + c * 1024;
#pragma unroll
        for (int j = 0; j < 4; j++) {
            int idx = tid + j * 256;
            CP16(bdst + idx * 16, (const void*)(bsrc + idx));
        }
        CPCOMMIT();
    };

    const int arow = tid >> 2, q = tid & 3;
    const float4* aldg = (const float4*)obase + (size_t)arow * 64 + q * 2;
    const uint32_t axor = (uint32_t)(((arow >> 1) & 3) << 4);
    const uint32_t asts_off = AH_OFF + (uint32_t)arow * 64 + (((uint32_t)q * 16) ^ axor);

    float4 pf[2][2];
    float sT = 0.f;
    auto ldgA = [&](int c, int slot) {
        pf[slot][0] = __ldg(aldg + c * 8);
        pf[slot][1] = __ldg(aldg + c * 8 + 1);
    };
    auto stsA = [&](int c, int slot) {
        const float4 u0 = *(const float4*)(ush + c * 32 + q * 8);
        const float4 u1 = *(const float4*)(ush + c * 32 + q * 8 + 4);
        float4 a0 = pf[slot][0], a1 = pf[slot][1];
        sT = fmaf(a0.x, u0.x, sT); sT = fmaf(a0.y, u0.y, sT);
        sT = fmaf(a0.z, u0.z, sT); sT = fmaf(a0.w, u0.w, sT);
        sT = fmaf(a1.x, u1.x, sT); sT = fmaf(a1.y, u1.y, sT);
        sT = fmaf(a1.z, u1.z, sT); sT = fmaf(a1.w, u1.w, sT);
        uint4 qq;
        qq.x = packh2(a0.x, a0.y); qq.y = packh2(a0.z, a0.w);
        qq.z = packh2(a1.x, a1.y); qq.w = packh2(a1.z, a1.w);
        *(uint4*)(smem + slot * 4096 + asts_off) = qq;
    };

    issueB(0); issueB(1);
    ush[tid] = __ldg(&g_u[b * HH + tid]);
    vsh[tid] = __ldg(&vF[tid]);
    ldgA(0, 0); ldgA(1, 1);
    __syncthreads();
    stsA(0, 0);

    uint32_t arow_l = (uint32_t)(mw * 32 + (lane & 7) + ((lane >> 3) & 1) * 8);
    uint32_t slot16 = (uint32_t)((lane >> 4) << 4);
    uint32_t lrow[2], lxor[2];
#pragma unroll
    for (int mi = 0; mi < 2; mi++) {
        uint32_t r = arow_l + mi * 16;
        lrow[mi] = sb + AH_OFF + r * 64;
        lxor[mi] = ((r >> 1) & 3) << 4;
    }

    float acc[2][8][4];
#pragma unroll
    for (int mi = 0; mi < 2; mi++)
#pragma unroll
        for (int ni = 0; ni < 8; ni++)
#pragma unroll
            for (int j = 0; j < 4; j++) acc[mi][ni][j] = 0.f;

#pragma unroll
    for (int c = 0; c < 8; c++) {
        if (c < 7) cpwait<1>(); else cpwait<0>();
        __syncthreads();
        if (c + 2 < 8) { issueB(c + 2); ldgA(c + 2, c & 1); }
        if (c + 1 < 8) stsA(c + 1, (c + 1) & 1);

        const uint4* Bsl = (const uint4*)(smem + B_OFF + (c % 3) * 16384);
        const uint32_t aoff = (uint32_t)((c & 1) * 4096);
#pragma unroll
        for (int t = 0; t < 2; t++) {
            uint32_t a[2][4];
#pragma unroll
            for (int mi = 0; mi < 2; mi++)
                ldsm4(a[mi], lrow[mi] + aoff + (((uint32_t)(32 * t) + slot16) ^ lxor[mi]));
            const uint4* bp = Bsl + (t * 16 + nw * 4) * 32 + lane;
#pragma unroll
            for (int p = 0; p < 4; p++) {
                uint4 bq = bp[p * 32];
#pragma unroll
                for (int mi = 0; mi < 2; mi++) {
                    mma16(acc[mi][2 * p],     a[mi][0], a[mi][1], a[mi][2], a[mi][3], bq.x, bq.y);
                    mma16(acc[mi][2 * p + 1], a[mi][0], a[mi][1], a[mi][2], a[mi][3], bq.z, bq.w);
                }
            }
        }
    }

#pragma unroll
    for (int mi = 0; mi < 2; mi++) {
        float s0a = 0.f, s1a = 0.f;
#pragma unroll
        for (int ni = 0; ni < 8; ni++) {
            int n = nw * 64 + ni * 8 + cq * 2;
            float v0 = vsh[n], v1 = vsh[n + 1];
            s0a = fmaf(tanha(acc[mi][ni][0]), v0, s0a);
            s0a = fmaf(tanha(acc[mi][ni][1]), v1, s0a);
            s1a = fmaf(tanha(acc[mi][ni][2]), v0, s1a);
            s1a = fmaf(tanha(acc[mi][ni][3]), v1, s1a);
        }
        s0a += __shfl_xor_sync(0xFFFFFFFFu, s0a, 1);
        s0a += __shfl_xor_sync(0xFFFFFFFFu, s0a, 2);
        s1a += __shfl_xor_sync(0xFFFFFFFFu, s1a, 1);
        s1a += __shfl_xor_sync(0xFFFFFFFFu, s1a, 2);
        if (cq == 0) {
            int r = mw * 32 + mi * 16 + rq;
            scFr[nw * 64 + r] = s0a;
            scFr[nw * 64 + r + 8] = s1a;
        }
    }

    sT += __shfl_xor_sync(0xFFFFFFFFu, sT, 1);
    sT += __shfl_xor_sync(0xFFFFFFFFu, sT, 2);
    if ((lane & 3) == 0) scT[arow] = sT;
    __syncthreads();
    if (tid < 64)
        scF[tid] = scFr[tid] + scFr[64 + tid] + scFr[128 + tid] + scFr[192 + tid];
    __syncthreads();

    float vv = 0.f, ee = 0.f;
    float* arr = (tid < 64) ? scT : scF;
    int i = tid & 63;
    if (tid < 128) {
        vv = arr[i];
        float m = vv;
#pragma unroll
        for (int off = 16; off; off >>= 1)
            m = fmaxf(m, __shfl_xor_sync(0xFFFFFFFFu, m, off));
        if (lane == 0) red[wid] = m;
    }
    __syncthreads();
    float M = 0.f;
    if (tid < 128) {
        M = (tid < 64) ? fmaxf(red[0], red[1]) : fmaxf(red[2], red[3]);
        ee = __expf(vv - M);
        float s = ee;
#pragma unroll
        for (int off = 16; off; off >>= 1)
            s += __shfl_xor_sync(0xFFFFFFFFu, s, off);
        if (lane == 0) red[16 + wid] = s;
    }
    __syncthreads();
    if (tid < 128) arr[i] = ee;
    __syncthreads();
    if (tid == 0)  { g_mT[tile] = M; g_sT[tile] = red[16] + red[17]; }
    if (tid == 64) { g_mF[tile] = M; g_sF[tile] = red[18] + red[19]; }

    {
        int g = tid >> 6, hc = tid & 63;
        const float4* orow = (const float4*)obase + (size_t)(g * 16) * 64 + hc;
        float4 aT = {0.f, 0.f, 0.f, 0.f}, aF = {0.f, 0.f, 0.f, 0.f};
#pragma unroll 8
        for (int r = 0; r < 16; r++) {
            float4 ov = __ldg(orow + (size_t)r * 64);
            float wT = scT[g * 16 + r], wF = scF[g * 16 + r];
            aT.x = fmaf(wT, ov.x, aT.x); aT.y = fmaf(wT, ov.y, aT.y);
            aT.z = fmaf(wT, ov.z, aT.z); aT.w = fmaf(wT, ov.w, aT.w);
            aF.x = fmaf(wF, ov.x, aF.x); aF.y = fmaf(wF, ov.y, aF.y);
            aF.z = fmaf(wF, ov.z, aF.z); aF.w = fmaf(wF, ov.w, aF.w);
        }
        float* pTs = (float*)(smem + PTS_OFF);
        float* pFs = (float*)(smem + PFS_OFF);
        ((float4*)(pTs + g * 256))[hc] = aT;
        ((float4*)(pFs + g * 256))[hc] = aF;
    }
    __syncthreads();
    {
        float* pTs = (float*)(smem + PTS_OFF);
        float* pFs = (float*)(smem + PFS_OFF);
        float a = pTs[tid] + pTs[256 + tid] + pTs[512 + tid] + pTs[768 + tid];
        float f = pFs[tid] + pFs[256 + tid] + pFs[512 + tid] + pFs[768 + tid];
        g_pT[tile * HH + tid] = a;
        g_pF[tile * HH + tid] = f;
    }
}

// ---------------------------------------------------------------------------
// k_combine: exact split-softmax merge over 64 s-tiles per batch.
// grid = (BB, 2), block = 1024. Quarter-block g handles tiles 16g..16g+15;
// partials merged through SMEM. Same fp32 math, reassociated across quarters.
// ---------------------------------------------------------------------------
__global__ void __launch_bounds__(1024)
k_combine(float* __restrict__ out) {
    __shared__ float sm_w[64];       // exp(m[c]-M) per tile
    __shared__ float sm_s[64];       // s[c]
    __shared__ float po[4][HH];      // partial weighted outputs
    int b = blockIdx.x, which = blockIdx.y;
    int tid = threadIdx.x;
    int g = tid >> 8, h = tid & 255;
    const float* gm = which ? g_mF : g_mT;
    const float* gs = which ? g_sF : g_sT;
    const float* gp = which ? g_pF : g_pT;

    if (tid < 64) {
        sm_w[tid] = __ldg(&gm[b * 64 + tid]);
        sm_s[tid] = __ldg(&gs[b * 64 + tid]);
    }
    __syncthreads();
    float M = -1e30f;
#pragma unroll
    for (int c = 0; c < 64; c++) M = fmaxf(M, sm_w[c]);
    __syncthreads();
    if (tid < 64) sm_w[tid] = __expf(sm_w[tid] - M);
    __syncthreads();

    float oV = 0.f;
#pragma unroll
    for (int cc = 0; cc < 16; cc++) {
        int c = g * 16 + cc;
        oV = fmaf(sm_w[c], __ldg(&gp[(b * 64 + c) * HH + h]), oV);
    }
    po[g][h] = oV;
    __syncthreads();
    if (tid < HH) {
        float S = 0.f;
#pragma unroll
        for (int c = 0; c < 64; c++) S = fmaf(sm_w[c], sm_s[c], S);
        float v = po[0][tid] + po[1][tid] + po[2][tid] + po[3][tid];
        out[b * 2 * HH + which * HH + tid] = v / S;
    }
}

// ---------------------------------------------------------------------------
extern "C" void kernel_launch(void* const* d_in, const int* in_sizes, int n_in,
                              void* d_out, int out_size) {
    const float* o  = (const float*)d_in[0];
    const float* Wt = (const float*)d_in[1];
    const float* WF = (const float*)d_in[2];
    const float* vF = (const float*)d_in[3];
    float* out = (float*)d_out;

    cudaFuncSetAttribute(k_main, cudaFuncAttributeMaxDynamicSharedMemorySize, SMEM_TOTAL);

    k_init<<<1040, 512>>>(o, Wt, WF);
    k_main<<<NTILES, 256, SMEM_TOTAL>>>(o, vF);
    k_combine<<<dim3(BB, 2), 1024>>>(out);
}

// round 12
// speedup vs baseline: 1.4772x; 1.0303x over previous
#include <cuda_runtime.h>
#include <cuda_fp16.h>
#include <math.h>
#include <stdint.h>

#define BB 64
#define SS 4096
#define HH 256
#define NTILES 4096            // BB*SS/64  (M=64 tiles)

// ---------------- device-global scratch (no allocation allowed) -------------
__device__ float g_u[BB * HH];            // W_t @ o_last per batch (fp32)
__device__ uint4 g_Bh[16 * 16 * 32];      // W_F fp16 m16n8k16 B-fragment image (128 KB)
__device__ float g_pT[NTILES * HH];
__device__ float g_pF[NTILES * HH];
__device__ float g_mT[NTILES], g_sT[NTILES], g_mF[NTILES], g_sF[NTILES];

// ---------------- SMEM map (bytes), 93824 total -> 2 CTAs/SM ----------------
#define AH_OFF    0            // 4 slots x 4096 (64 rows x 64B fp16) = 16384
#define B_OFF     16384        // 4 slots x 16384 = 65536 (fp16 fragments)
#define USH_OFF   81920        // 256 floats
#define VSH_OFF   82944        // 256 floats
#define SCT_OFF   83968        // 64 floats
#define SCF_OFF   84224        // 64 floats
#define SCFR_OFF  84480        // 4 x 64 floats = 1024
#define RED_OFF   85504        // 32 floats
#define PTS_OFF   85632        // 4 x 256 floats = 4096
#define PFS_OFF   89728        // 4 x 256 floats = 4096
#define SMEM_TOTAL 93824

// ---------------- helpers ----------------------------------------------------
__device__ __forceinline__ uint32_t packh2(float lo, float hi) {
    __half2 h = __floats2half2_rn(lo, hi);
    return *(uint32_t*)&h;
}
__device__ __forceinline__ float tanha(float x) {
    float y;
    asm("tanh.approx.f32 %0, %1;" : "=f"(y) : "f"(x));
    return y;
}
__device__ __forceinline__ void mma16(float* c, uint32_t a0, uint32_t a1,
                                      uint32_t a2, uint32_t a3,
                                      uint32_t b0, uint32_t b1) {
    asm volatile(
        "mma.sync.aligned.m16n8k16.row.col.f32.f16.f16.f32 "
        "{%0,%1,%2,%3}, {%4,%5,%6,%7}, {%8,%9}, {%0,%1,%2,%3};"
        : "+f"(c[0]), "+f"(c[1]), "+f"(c[2]), "+f"(c[3])
        : "r"(a0), "r"(a1), "r"(a2), "r"(a3), "r"(b0), "r"(b1));
}
__device__ __forceinline__ void ldsm4(uint32_t* a, uint32_t addr) {
    asm volatile("ldmatrix.sync.aligned.m8n8.x4.shared.b16 {%0,%1,%2,%3}, [%4];"
                 : "=r"(a[0]), "=r"(a[1]), "=r"(a[2]), "=r"(a[3]) : "r"(addr));
}
#define CP16(dst, src) \
    asm volatile("cp.async.cg.shared.global [%0], [%1], 16;" :: "r"(dst), "l"(src) : "memory")
#define CPCOMMIT() asm volatile("cp.async.commit_group;" ::: "memory")
template<int N> __device__ __forceinline__ void cpwait() {
    asm volatile("cp.async.wait_group %0;" :: "n"(N) : "memory");
}
__device__ __forceinline__ uint32_t s2u(const void* p) {
    uint32_t a;
    asm("{ .reg .u64 t; cvta.to.shared.u64 t, %1; cvt.u32.u64 %0, t; }" : "=r"(a) : "l"(p));
    return a;
}

// ---------------------------------------------------------------------------
// k_init: blocks 0..15 build the W_F fp16 B-fragment image;
//         blocks 16..1039 compute u[b][h] via coalesced warp-dot.
// ---------------------------------------------------------------------------
__global__ void __launch_bounds__(512)
k_init(const float* __restrict__ o, const float* __restrict__ Wt,
       const float* __restrict__ WF) {
    int tid = threadIdx.x;
    if (blockIdx.x < 16) {
        int t = blockIdx.x;
        int p = tid >> 5, l = tid & 31;
        int rq = l >> 2, cq = l & 3;
        int k0 = t * 16 + 2 * cq;
        int na = p * 16 + rq, nb = na + 8;
        uint4 q;
        q.x = packh2(WF[k0 * HH + na],       WF[(k0 + 1) * HH + na]);
        q.y = packh2(WF[(k0 + 8) * HH + na], WF[(k0 + 9) * HH + na]);
        q.z = packh2(WF[k0 * HH + nb],       WF[(k0 + 1) * HH + nb]);
        q.w = packh2(WF[(k0 + 8) * HH + nb], WF[(k0 + 9) * HH + nb]);
        g_Bh[(t * 16 + p) * 32 + l] = q;
    } else {
        int idx = (blockIdx.x - 16) * 16 + (tid >> 5);
        int lane = tid & 31;
        int b = idx >> 8, h = idx & 255;
        const float* wrow = Wt + h * HH;
        const float* olast = o + ((size_t)b * SS + (SS - 1)) * HH;
        float acc = 0.f;
#pragma unroll
        for (int j = 0; j < 8; j++) {
            int k = j * 32 + lane;
            acc = fmaf(__ldg(&wrow[k]), __ldg(&olast[k]), acc);
        }
#pragma unroll
        for (int off = 16; off; off >>= 1)
            acc += __shfl_xor_sync(0xFFFFFFFFu, acc, off);
        if (lane == 0) g_u[b * HH + h] = acc;
    }
}

// ---------------------------------------------------------------------------
// k_main: M=64 tile, 256 threads, 2 CTAs/SM. Mainloop restructured into
//         2-chunk bodies: ONE barrier per 2 K-chunks, 4-slot A and B rings.
// grid=4096, block=256.
// ---------------------------------------------------------------------------
__global__ void __launch_bounds__(256, 2)
k_main(const float* __restrict__ o, const float* __restrict__ vF) {
    extern __shared__ __align__(16) char smem[];
    const uint32_t sb = s2u(smem);
    const int tid = threadIdx.x, lane = tid & 31, wid = tid >> 5;
    const int tile = blockIdx.x;
    const int b = tile >> 6, s0 = (tile & 63) << 6;
    const int mw = wid & 1;   // M half (32 rows)
    const int nw = wid >> 1;  // N quarter (64 cols)
    const int rq = lane >> 2, cq = lane & 3;

    float* ush  = (float*)(smem + USH_OFF);
    float* vsh  = (float*)(smem + VSH_OFF);
    float* scT  = (float*)(smem + SCT_OFF);
    float* scF  = (float*)(smem + SCF_OFF);
    float* scFr = (float*)(smem + SCFR_OFF);
    float* red  = (float*)(smem + RED_OFF);

    const float* obase = o + ((size_t)(b * SS + s0)) * HH;

    // ---- B chunk issue via cp.async into slot (c & 3) ----
    auto issueB = [&](int c) {
        uint32_t bdst = sb + B_OFF + (c & 3) * 16384;
        const uint4* bsrc = g_Bh + c * 1024;
#pragma unroll
        for (int j = 0; j < 4; j++) {
            int idx = tid + j * 256;
            CP16(bdst + idx * 16, (const void*)(bsrc + idx));
        }
        CPCOMMIT();
    };

    // ---- A prefetch (LDG->fp32 regs), fold time-score FMAs, fp16 STS ----
    const int arow = tid >> 2, q = tid & 3;
    const float4* aldg = (const float4*)obase + (size_t)arow * 64 + q * 2;
    const uint32_t axor = (uint32_t)(((arow >> 1) & 3) << 4);
    const uint32_t asts_off = AH_OFF + (uint32_t)arow * 64 + (((uint32_t)q * 16) ^ axor);

    float4 pf[2][2];          // pf slot = chunk & 1
    float sT = 0.f;
    auto ldgA = [&](int c) {
        pf[c & 1][0] = __ldg(aldg + c * 8);
        pf[c & 1][1] = __ldg(aldg + c * 8 + 1);
    };
    auto stsA = [&](int c) {  // writes A slot (c & 3), consumes pf[c & 1]
        const float4 u0 = *(const float4*)(ush + c * 32 + q * 8);
        const float4 u1 = *(const float4*)(ush + c * 32 + q * 8 + 4);
        float4 a0 = pf[c & 1][0], a1 = pf[c & 1][1];
        sT = fmaf(a0.x, u0.x, sT); sT = fmaf(a0.y, u0.y, sT);
        sT = fmaf(a0.z, u0.z, sT); sT = fmaf(a0.w, u0.w, sT);
        sT = fmaf(a1.x, u1.x, sT); sT = fmaf(a1.y, u1.y, sT);
        sT = fmaf(a1.z, u1.z, sT); sT = fmaf(a1.w, u1.w, sT);
        uint4 qq;
        qq.x = packh2(a0.x, a0.y); qq.y = packh2(a0.z, a0.w);
        qq.z = packh2(a1.x, a1.y); qq.w = packh2(a1.z, a1.w);
        *(uint4*)(smem + (c & 3) * 4096 + asts_off) = qq;
    };

    // ---- prologue ----
    issueB(0); issueB(1);
    ush[tid] = __ldg(&g_u[b * HH + tid]);
    vsh[tid] = __ldg(&vF[tid]);
    ldgA(0); ldgA(1);
    __syncthreads();          // ush visible before stsA(0)
    stsA(0); ldgA(2);
    stsA(1); ldgA(3);

    // ---- ldmatrix lane addressing (per mi) ----
    uint32_t arow_l = (uint32_t)(mw * 32 + (lane & 7) + ((lane >> 3) & 1) * 8);
    uint32_t slot16 = (uint32_t)((lane >> 4) << 4);
    uint32_t lrow[2], lxor[2];
#pragma unroll
    for (int mi = 0; mi < 2; mi++) {
        uint32_t r = arow_l + mi * 16;
        lrow[mi] = sb + AH_OFF + r * 64;
        lxor[mi] = ((r >> 1) & 3) << 4;
    }

    float acc[2][8][4];
#pragma unroll
    for (int mi = 0; mi < 2; mi++)
#pragma unroll
        for (int ni = 0; ni < 8; ni++)
#pragma unroll
            for (int j = 0; j < 4; j++) acc[mi][ni][j] = 0.f;

    // ---- mainloop: 4 bodies of 2 K-chunks each ----
#pragma unroll
    for (int c = 0; c < 8; c += 2) {
        cpwait<0>();           // B(c), B(c+1) complete (only groups outstanding)
        __syncthreads();       // B visible to all warps; all warps done body c-2
        if (c + 2 < 8) {
            issueB(c + 2); issueB(c + 3);          // slots last read at c-2/c-1
            stsA(c + 2);                            // A slot (c+2)&3, pf[c&1]
            if (c + 4 < 8) ldgA(c + 4);
            stsA(c + 3);
            if (c + 5 < 8) ldgA(c + 5);
        }
#pragma unroll
        for (int s = 0; s < 2; s++) {
            const int cc = c + s;
            const uint4* Bsl = (const uint4*)(smem + B_OFF + (cc & 3) * 16384);
            const uint32_t aoff = (uint32_t)((cc & 3) * 4096);
#pragma unroll
            for (int t = 0; t < 2; t++) {
                uint32_t a[2][4];
#pragma unroll
                for (int mi = 0; mi < 2; mi++)
                    ldsm4(a[mi], lrow[mi] + aoff + (((uint32_t)(32 * t) + slot16) ^ lxor[mi]));
                const uint4* bp = Bsl + (t * 16 + nw * 4) * 32 + lane;
#pragma unroll
                for (int p = 0; p < 4; p++) {
                    uint4 bq = bp[p * 32];
#pragma unroll
                    for (int mi = 0; mi < 2; mi++) {
                        mma16(acc[mi][2 * p],     a[mi][0], a[mi][1], a[mi][2], a[mi][3], bq.x, bq.y);
                        mma16(acc[mi][2 * p + 1], a[mi][0], a[mi][1], a[mi][2], a[mi][3], bq.z, bq.w);
                    }
                }
            }
        }
    }

    // ---- feature scores: sf[r] = sum_n tanh(z[r,n]) * v[n] ----
#pragma unroll
    for (int mi = 0; mi < 2; mi++) {
        float s0a = 0.f, s1a = 0.f;
#pragma unroll
        for (int ni = 0; ni < 8; ni++) {
            int n = nw * 64 + ni * 8 + cq * 2;
            float v0 = vsh[n], v1 = vsh[n + 1];
            s0a = fmaf(tanha(acc[mi][ni][0]), v0, s0a);
            s0a = fmaf(tanha(acc[mi][ni][1]), v1, s0a);
            s1a = fmaf(tanha(acc[mi][ni][2]), v0, s1a);
            s1a = fmaf(tanha(acc[mi][ni][3]), v1, s1a);
        }
        s0a += __shfl_xor_sync(0xFFFFFFFFu, s0a, 1);
        s0a += __shfl_xor_sync(0xFFFFFFFFu, s0a, 2);
        s1a += __shfl_xor_sync(0xFFFFFFFFu, s1a, 1);
        s1a += __shfl_xor_sync(0xFFFFFFFFu, s1a, 2);
        if (cq == 0) {
            int r = mw * 32 + mi * 16 + rq;
            scFr[nw * 64 + r] = s0a;
            scFr[nw * 64 + r + 8] = s1a;
        }
    }

    // ---- exact fp32 time scores: reduce 4 threads sharing a row ----
    sT += __shfl_xor_sync(0xFFFFFFFFu, sT, 1);
    sT += __shfl_xor_sync(0xFFFFFFFFu, sT, 2);
    if ((lane & 3) == 0) scT[arow] = sT;
    __syncthreads();
    if (tid < 64)
        scF[tid] = scFr[tid] + scFr[64 + tid] + scFr[128 + tid] + scFr[192 + tid];
    __syncthreads();

    // ---- split-softmax partials (threads 0..127: warps 0-1 T, 2-3 F) ----
    float vv = 0.f, ee = 0.f;
    float* arr = (tid < 64) ? scT : scF;
    int i = tid & 63;
    if (tid < 128) {
        vv = arr[i];
        float m = vv;
#pragma unroll
        for (int off = 16; off; off >>= 1)
            m = fmaxf(m, __shfl_xor_sync(0xFFFFFFFFu, m, off));
        if (lane == 0) red[wid] = m;
    }
    __syncthreads();
    float M = 0.f;
    if (tid < 128) {
        M = (tid < 64) ? fmaxf(red[0], red[1]) : fmaxf(red[2], red[3]);
        ee = __expf(vv - M);
        float s = ee;
#pragma unroll
        for (int off = 16; off; off >>= 1)
            s += __shfl_xor_sync(0xFFFFFFFFu, s, off);
        if (lane == 0) red[16 + wid] = s;
    }
    __syncthreads();
    if (tid < 128) arr[i] = ee;
    __syncthreads();
    if (tid == 0)  { g_mT[tile] = M; g_sT[tile] = red[16] + red[17]; }
    if (tid == 64) { g_mF[tile] = M; g_sF[tile] = red[18] + red[19]; }

    // ---- exact fp32 weighted sums: re-read o (L2-hot) via LDG.128 ----
    {
        int g = tid >> 6, hc = tid & 63;
        const float4* orow = (const float4*)obase + (size_t)(g * 16) * 64 + hc;
        float4 aT = {0.f, 0.f, 0.f, 0.f}, aF = {0.f, 0.f, 0.f, 0.f};
#pragma unroll 8
        for (int r = 0; r < 16; r++) {
            float4 ov = __ldg(orow + (size_t)r * 64);
            float wT = scT[g * 16 + r], wF = scF[g * 16 + r];
            aT.x = fmaf(wT, ov.x, aT.x); aT.y = fmaf(wT, ov.y, aT.y);
            aT.z = fmaf(wT, ov.z, aT.z); aT.w = fmaf(wT, ov.w, aT.w);
            aF.x = fmaf(wF, ov.x, aF.x); aF.y = fmaf(wF, ov.y, aF.y);
            aF.z = fmaf(wF, ov.z, aF.z); aF.w = fmaf(wF, ov.w, aF.w);
        }
        float* pTs = (float*)(smem + PTS_OFF);
        float* pFs = (float*)(smem + PFS_OFF);
        ((float4*)(pTs + g * 256))[hc] = aT;
        ((float4*)(pFs + g * 256))[hc] = aF;
    }
    __syncthreads();
    {
        float* pTs = (float*)(smem + PTS_OFF);
        float* pFs = (float*)(smem + PFS_OFF);
        float a = pTs[tid] + pTs[256 + tid] + pTs[512 + tid] + pTs[768 + tid];
        float f = pFs[tid] + pFs[256 + tid] + pFs[512 + tid] + pFs[768 + tid];
        g_pT[tile * HH + tid] = a;
        g_pF[tile * HH + tid] = f;
    }
}

// ---------------------------------------------------------------------------
// k_combine: exact split-softmax merge over 64 s-tiles per batch.
// grid = (BB, 2), block = 1024.
// ---------------------------------------------------------------------------
__global__ void __launch_bounds__(1024)
k_combine(float* __restrict__ out) {
    __shared__ float sm_w[64];
    __shared__ float sm_s[64];
    __shared__ float po[4][HH];
    int b = blockIdx.x, which = blockIdx.y;
    int tid = threadIdx.x;
    int g = tid >> 8, h = tid & 255;
    const float* gm = which ? g_mF : g_mT;
    const float* gs = which ? g_sF : g_sT;
    const float* gp = which ? g_pF : g_pT;

    if (tid < 64) {
        sm_w[tid] = __ldg(&gm[b * 64 + tid]);
        sm_s[tid] = __ldg(&gs[b * 64 + tid]);
    }
    __syncthreads();
    float M = -1e30f;
#pragma unroll
    for (int c = 0; c < 64; c++) M = fmaxf(M, sm_w[c]);
    __syncthreads();
    if (tid < 64) sm_w[tid] = __expf(sm_w[tid] - M);
    __syncthreads();

    float oV = 0.f;
#pragma unroll
    for (int cc = 0; cc < 16; cc++) {
        int c = g * 16 + cc;
        oV = fmaf(sm_w[c], __ldg(&gp[(b * 64 + c) * HH + h]), oV);
    }
    po[g][h] = oV;
    __syncthreads();
    if (tid < HH) {
        float S = 0.f;
#pragma unroll
        for (int c = 0; c < 64; c++) S = fmaf(sm_w[c], sm_s[c], S);
        float v = po[0][tid] + po[1][tid] + po[2][tid] + po[3][tid];
        out[b * 2 * HH + which * HH + tid] = v / S;
    }
}

// ---------------------------------------------------------------------------
extern "C" void kernel_launch(void* const* d_in, const int* in_sizes, int n_in,
                              void* d_out, int out_size) {
    const float* o  = (const float*)d_in[0];
    const float* Wt = (const float*)d_in[1];
    const float* WF = (const float*)d_in[2];
    const float* vF = (const float*)d_in[3];
    float* out = (float*)d_out;

    cudaFuncSetAttribute(k_main, cudaFuncAttributeMaxDynamicSharedMemorySize, SMEM_TOTAL);

    k_init<<<1040, 512>>>(o, Wt, WF);
    k_main<<<NTILES, 256, SMEM_TOTAL>>>(o, vF);
    k_combine<<<dim3(BB, 2), 1024>>>(out);
}